// round 1
// baseline (speedup 1.0000x reference)
#include <cuda_runtime.h>
#include <cuda_bf16.h>
#include <math.h>

// Problem constants
#define BB 2
#define SS 2048
#define HH 16
#define DD 128
#define HD 2048
#define WIN 256
#define GG 64

// Scratch (device globals: allocation-free rule)
__device__ float g_qkv[(size_t)BB * SS * 3 * HD];   // [B,S,6144]
__device__ float g_q[(size_t)BB * HH * SS * DD];    // [B,H,S,D] roped q
__device__ float g_km[(size_t)BB * SS * DD];        // k_mean (roped)
__device__ float g_vm[(size_t)BB * SS * DD];        // v_mean
__device__ float g_attn[(size_t)BB * SS * HD];      // [B,S,H*D] attention out

// ---------------------------------------------------------------------------
// Classic 128x128x8 register-tiled SGEMM, row-major A[M,K] * B[K,N] + bias
// ---------------------------------------------------------------------------
__global__ __launch_bounds__(256)
void sgemm_bias_kernel(const float* __restrict__ A, const float* __restrict__ B,
                       const float* __restrict__ bias, float* __restrict__ C,
                       int M, int N, int K)
{
    __shared__ float As[8][128];
    __shared__ float Bs[8][128];

    const int tid = threadIdx.x;
    const int brow = blockIdx.y;
    const int bcol = blockIdx.x;

    const float* Ab = A + (size_t)brow * 128 * K;
    const float* Bb = B + (size_t)bcol * 128;

    const int aRow = tid >> 1;            // 0..127
    const int aCol = (tid & 1) * 4;       // 0 or 4
    const int bRow = tid >> 5;            // 0..7
    const int bCol = (tid & 31) * 4;      // 0..124

    const int tr = (tid >> 4) * 8;        // 0..120
    const int tc = (tid & 15) * 8;        // 0..120

    float acc[8][8];
#pragma unroll
    for (int i = 0; i < 8; i++)
#pragma unroll
        for (int j = 0; j < 8; j++) acc[i][j] = 0.f;

    for (int k0 = 0; k0 < K; k0 += 8) {
        float4 av = *(const float4*)(Ab + (size_t)aRow * K + k0 + aCol);
        As[aCol + 0][aRow] = av.x;
        As[aCol + 1][aRow] = av.y;
        As[aCol + 2][aRow] = av.z;
        As[aCol + 3][aRow] = av.w;
        float4 bv = *(const float4*)(Bb + (size_t)(k0 + bRow) * N + bCol);
        *(float4*)&Bs[bRow][bCol] = bv;
        __syncthreads();

#pragma unroll
        for (int k = 0; k < 8; k++) {
            float ra[8], rb[8];
            *(float4*)&ra[0] = *(const float4*)&As[k][tr];
            *(float4*)&ra[4] = *(const float4*)&As[k][tr + 4];
            *(float4*)&rb[0] = *(const float4*)&Bs[k][tc];
            *(float4*)&rb[4] = *(const float4*)&Bs[k][tc + 4];
#pragma unroll
            for (int i = 0; i < 8; i++)
#pragma unroll
                for (int j = 0; j < 8; j++) acc[i][j] += ra[i] * rb[j];
        }
        __syncthreads();
    }

#pragma unroll
    for (int i = 0; i < 8; i++) {
        float* crow = C + (size_t)(brow * 128 + tr + i) * N + bcol * 128 + tc;
        const float* brow_b = bias + bcol * 128 + tc;
#pragma unroll
        for (int j = 0; j < 8; j += 4) {
            float4 v;
            v.x = acc[i][j + 0] + brow_b[j + 0];
            v.y = acc[i][j + 1] + brow_b[j + 1];
            v.z = acc[i][j + 2] + brow_b[j + 2];
            v.w = acc[i][j + 3] + brow_b[j + 3];
            *(float4*)(crow + j) = v;
        }
    }
}

// ---------------------------------------------------------------------------
// RoPE + split + head-mean.  One block per (b,s), 128 threads (= dim d).
// RoPE is linear with per-position coefficients shared across heads, so
// rope(mean_h(k)) == mean_h(rope(k)).
// ---------------------------------------------------------------------------
__global__ __launch_bounds__(128)
void rope_split_mean_kernel(const float* __restrict__ qkv,
                            float* __restrict__ qout,
                            float* __restrict__ km,
                            float* __restrict__ vm)
{
    int bs = blockIdx.x;                 // 0..4095
    int b = bs >> 11, s = bs & 2047;
    int d = threadIdx.x;                 // 0..127
    const float* base = qkv + (size_t)bs * 6144;

    float c = 1.f, sn = 0.f;
    float sgn = (d < 16) ? -1.f : 1.f;
    if (d < 32) {
        // inv_freq = 10000^(-(d%16)/16), computed precisely; trig in fp64 so
        // --use_fast_math cannot degrade range reduction at ang ~ 2047 rad.
        float invf = (float)exp2(-(double)(d & 15) / 16.0 * log2(10000.0));
        float ang = (float)s * invf;     // fp32 multiply matches reference
        c = (float)cos((double)ang);
        sn = (float)sin((double)ang);
    }

    float ks = 0.f, vs = 0.f;
#pragma unroll
    for (int h = 0; h < 16; ++h) {
        ks += base[h * 384 + 128 + d];
        vs += base[h * 384 + 256 + d];
    }
    ks *= 0.0625f; vs *= 0.0625f;

    float kp = __shfl_xor_sync(0xffffffffu, ks, 16);  // rope partner (d ^ 16)
    if (d < 32) ks = ks * c + sgn * kp * sn;
    km[(size_t)bs * 128 + d] = ks;
    vm[(size_t)bs * 128 + d] = vs;

#pragma unroll
    for (int h = 0; h < 16; ++h) {
        float qv = base[h * 384 + d];
        float qp = __shfl_xor_sync(0xffffffffu, qv, 16);
        float qr = (d < 32) ? (qv * c + sgn * qp * sn) : qv;
        qout[(((size_t)(b * 16 + h)) * SS + s) * 128 + d] = qr;
    }
}

// ---------------------------------------------------------------------------
// Attention. One block per (b, qpos); 256 threads; all 16 heads share K/V.
//   qpos <  256: causal prefix over k_mean[0..qpos] (+ attention_mask)
//   qpos >= 256: t = qpos-256; 64 global keys (valid iff glob_idx < t)
//                + window keys t+1..t+256 (+ attention_mask)
// Dynamic smem layout (floats):
//   qs[16*128] | sc[16*320] | kt[64*129] | kadd[320] | kpos[320](int)
// ---------------------------------------------------------------------------
#define ATTN_SMEM_FLOATS (16*128 + 16*320 + 64*129 + 320 + 320)

__global__ __launch_bounds__(256)
void attn_kernel(const float* __restrict__ q,
                 const float* __restrict__ km,
                 const float* __restrict__ vm,
                 const float* __restrict__ mask,
                 const int* __restrict__ gidx,
                 float* __restrict__ out)
{
    extern __shared__ float sm[];
    float* qs = sm;                       // 2048
    float* sc = sm + 2048;                // 5120
    float* kt = sm + 2048 + 5120;         // 64*129 = 8256
    float* kadd = kt + 64 * 129;          // 320
    int* kpos = (int*)(kadd + 320);       // 320

    const int bq = blockIdx.x;
    const int b = bq >> 11;
    const int qp = bq & 2047;
    const int tid = threadIdx.x;

    // load q for all heads (q layout [B,H,S,D])
    {
        int h = tid >> 4, d0 = (tid & 15) * 8;
        const float* src = q + (((size_t)(b * 16 + h)) * SS + qp) * 128 + d0;
        *(float4*)(qs + h * 128 + d0)     = *(const float4*)src;
        *(float4*)(qs + h * 128 + d0 + 4) = *(const float4*)(src + 4);
    }

    int ng, nw, wstart, tstep;
    if (qp < WIN) { ng = 0; nw = qp + 1; wstart = 0; tstep = -1; }
    else { ng = GG; nw = WIN; tstep = qp - WIN; wstart = tstep + 1; }
    const int nk = ng + nw;
    const int nchunk = (nk + 63) >> 6;

    const float scale = 0.08838834764831845f;  // 1/sqrt(128)
    const float NEG = -1e30f;

    // ---- K phase: scores ----
    for (int c = 0; c < nchunk; ++c) {
        int cb = c << 6;
        __syncthreads();
        if (tid < 64) {
            int jk = cb + tid;
            int pos = 0; float add = NEG;
            if (jk < nk) {
                if (jk < ng) {
                    pos = gidx[b * 64 + jk];
                    add = (pos < tstep) ? 0.f : NEG;
                } else {
                    pos = wstart + (jk - ng);
                    add = mask[b * SS + pos];
                }
            }
            kpos[jk] = pos;
            kadd[jk] = add;
        }
        __syncthreads();
        // cooperative load of 64 k rows
        {
            int row = tid >> 2, q4 = tid & 3;
            int pos = kpos[cb + row];
            const float* src = km + ((size_t)b * SS + pos) * 128;
            float* dstrow = kt + row * 129;
#pragma unroll
            for (int i = 0; i < 8; ++i) {
                int off = (q4 + (i << 2)) * 4;
                float4 v = *(const float4*)(src + off);
                dstrow[off + 0] = v.x; dstrow[off + 1] = v.y;
                dstrow[off + 2] = v.z; dstrow[off + 3] = v.w;
            }
        }
        __syncthreads();
        // 2 heads x 2 keys per thread (keys lane, lane+32 -> conflict-free)
        {
            int h0 = (tid >> 5) << 1;
            int j0 = tid & 31, j1 = j0 + 32;
            float s00 = 0, s01 = 0, s10 = 0, s11 = 0;
            const float* qa = qs + h0 * 128;
            const float* qb = qa + 128;
            const float* k0 = kt + j0 * 129;
            const float* k1 = kt + j1 * 129;
#pragma unroll 4
            for (int d = 0; d < 128; ++d) {
                float a0 = qa[d], a1 = qb[d];
                float b0 = k0[d], b1 = k1[d];
                s00 += a0 * b0; s01 += a0 * b1;
                s10 += a1 * b0; s11 += a1 * b1;
            }
            float ad0 = kadd[cb + j0], ad1 = kadd[cb + j1];
            sc[h0 * 320 + cb + j0] = s00 * scale + ad0;
            sc[h0 * 320 + cb + j1] = s01 * scale + ad1;
            sc[(h0 + 1) * 320 + cb + j0] = s10 * scale + ad0;
            sc[(h0 + 1) * 320 + cb + j1] = s11 * scale + ad1;
        }
    }
    __syncthreads();

    // ---- softmax: warp w handles heads 2w, 2w+1 ----
    {
        int w = tid >> 5, lane = tid & 31;
        int ntot = nchunk << 6;
        for (int hh = 0; hh < 2; ++hh) {
            float* row = sc + (w * 2 + hh) * 320;
            float m = -3.4e38f;
            for (int j = lane; j < ntot; j += 32) m = fmaxf(m, row[j]);
#pragma unroll
            for (int o = 16; o > 0; o >>= 1) m = fmaxf(m, __shfl_xor_sync(0xffffffffu, m, o));
            float sum = 0.f;
            for (int j = lane; j < ntot; j += 32) {
                float e = __expf(row[j] - m);
                row[j] = e; sum += e;
            }
#pragma unroll
            for (int o = 16; o > 0; o >>= 1) sum += __shfl_xor_sync(0xffffffffu, sum, o);
            float inv = 1.f / sum;
            for (int j = lane; j < ntot; j += 32) row[j] *= inv;
        }
    }

    // ---- V phase: thread owns (h = tid>>4, dims d = (tid&15)+16i) ----
    float acc[8] = {0, 0, 0, 0, 0, 0, 0, 0};
    const int h = tid >> 4, dl = tid & 15;
    for (int c = 0; c < nchunk; ++c) {
        int cb = c << 6;
        __syncthreads();
        {
            int row = tid >> 2, q4 = tid & 3;
            int pos = kpos[cb + row];
            const float* src = vm + ((size_t)b * SS + pos) * 128;
            float* dstrow = kt + row * 129;
#pragma unroll
            for (int i = 0; i < 8; ++i) {
                int off = (q4 + (i << 2)) * 4;
                float4 v = *(const float4*)(src + off);
                dstrow[off + 0] = v.x; dstrow[off + 1] = v.y;
                dstrow[off + 2] = v.z; dstrow[off + 3] = v.w;
            }
        }
        __syncthreads();
        const float* wrow = sc + h * 320 + cb;
#pragma unroll 2
        for (int j = 0; j < 64; ++j) {
            float wv = wrow[j];
            const float* vr = kt + j * 129 + dl;
#pragma unroll
            for (int i = 0; i < 8; ++i) acc[i] += wv * vr[i * 16];
        }
    }

    // write [B,S,H*D]
    float* o = out + ((size_t)b * SS + qp) * HD + h * 128 + dl;
#pragma unroll
    for (int i = 0; i < 8; ++i) o[i * 16] = acc[i];
}

// ---------------------------------------------------------------------------
extern "C" void kernel_launch(void* const* d_in, const int* in_sizes, int n_in,
                              void* d_out, int out_size)
{
    const float* hidden = (const float*)d_in[0];
    const float* mask   = (const float*)d_in[1];
    const int*   gidx   = (const int*)d_in[2];
    const float* Wqkv   = (const float*)d_in[3];
    const float* bqkv   = (const float*)d_in[4];
    const float* Wo     = (const float*)d_in[5];
    const float* bo     = (const float*)d_in[6];
    float* out = (float*)d_out;

    float *qkv, *qbuf, *kmp, *vmp, *attn;
    cudaGetSymbolAddress((void**)&qkv,  g_qkv);
    cudaGetSymbolAddress((void**)&qbuf, g_q);
    cudaGetSymbolAddress((void**)&kmp,  g_km);
    cudaGetSymbolAddress((void**)&vmp,  g_vm);
    cudaGetSymbolAddress((void**)&attn, g_attn);

    const int smem_attn = ATTN_SMEM_FLOATS * 4;
    cudaFuncSetAttribute(attn_kernel, cudaFuncAttributeMaxDynamicSharedMemorySize,
                         smem_attn);

    // 1) QKV GEMM: [4096,2048] @ [2048,6144] + b
    sgemm_bias_kernel<<<dim3(6144 / 128, 4096 / 128), 256>>>(
        hidden, Wqkv, bqkv, qkv, 4096, 6144, 2048);

    // 2) RoPE + split + head-mean
    rope_split_mean_kernel<<<BB * SS, 128>>>(qkv, qbuf, kmp, vmp);

    // 3) Attention (all heads per block; K/V shared across heads)
    attn_kernel<<<BB * SS, 256, smem_attn>>>(qbuf, kmp, vmp, mask, gidx, attn);

    // 4) Output GEMM: [4096,2048] @ [2048,2048] + b
    sgemm_bias_kernel<<<dim3(2048 / 128, 4096 / 128), 256>>>(
        attn, Wo, bo, out, 4096, 2048, 2048);
}

// round 3
// speedup vs baseline: 1.0031x; 1.0031x over previous
#include <cuda_runtime.h>
#include <cuda_bf16.h>
#include <cstdint>
#include <math.h>

// Problem constants
#define BB 2
#define SS 2048
#define HH 16
#define DD 128
#define HD 2048
#define WIN 256
#define GG 64

// Scratch (device globals: allocation-free rule)
__device__ float g_qkv[(size_t)BB * SS * 3 * HD];   // [B,S,6144]
__device__ float g_q[(size_t)BB * HH * SS * DD];    // [B,H,S,D] roped q
__device__ float g_km[(size_t)BB * SS * DD];        // k_mean (roped)
__device__ float g_vm[(size_t)BB * SS * DD];        // v_mean
__device__ float g_attn[(size_t)BB * SS * HD];      // [B,S,H*D] attention out

// ---------------------------------------------------------------------------
// TF32 tensor-core GEMM: C[M,N] = A[M,K] @ B[K,N] + bias, all row-major fp32.
// 128x128 block tile, BK=16, 8 warps (each 64x32 via mma.sync.m16n8k8.tf32).
// Smem is stored in FRAGMENT-PERMUTED order so the inner loop reads each
// A-fragment as one float4 per lane and each B-fragment as one float2 per
// lane (conflict-free, no ldmatrix). Double-buffered, 1 sync per K-tile.
// Requires M%128==0, N%128==0, K%16==0.
// ---------------------------------------------------------------------------
__device__ __forceinline__ float cvt_tf32(float v) {
    unsigned int t;
    asm("cvt.rna.tf32.f32 %0, %1;" : "=r"(t) : "f"(v));
    return __uint_as_float(t);
}

__global__ __launch_bounds__(256)
void tf32_gemm_bias(const float* __restrict__ A, const float* __restrict__ B,
                    const float* __restrict__ bias, float* __restrict__ C,
                    int M, int N, int K)
{
    __shared__ float As[2][2048];   // [ks(2)][mi(8)][lane(32)][reg(4)]
    __shared__ float Bs[2][2048];   // [ks(2)][ni(16)][lane(32)][reg(2)]

    const int tid  = threadIdx.x;
    const int lane = tid & 31;
    const int warp = tid >> 5;
    const int wm = warp >> 2;       // 0..1  (m half)
    const int wn = warp & 3;        // 0..3  (n quarter)
    const int brow = blockIdx.y, bcol = blockIdx.x;

    const float* Ab = A + (size_t)brow * 128 * K;
    const float* Bb = B + (size_t)bcol * 128;

    float acc[4][4][4];
#pragma unroll
    for (int i = 0; i < 4; i++)
#pragma unroll
        for (int j = 0; j < 4; j++)
#pragma unroll
            for (int r = 0; r < 4; r++) acc[i][j][r] = 0.f;

    float4 ra[2], rb[2];

    const int nk = K >> 4;

    // ---- load tile kt into registers ----
    auto load_tile = [&](int kt) {
        int k0 = kt << 4;
#pragma unroll
        for (int l = 0; l < 2; ++l) {
            int f4 = l * 256 + tid;              // 0..511
            int r  = f4 >> 2, c0 = (f4 & 3) * 4; // A: 128x16
            ra[l] = *(const float4*)(Ab + (size_t)r * K + k0 + c0);
            int kk = f4 >> 5, n0 = (f4 & 31) * 4; // B: 16x128
            rb[l] = *(const float4*)(Bb + (size_t)(k0 + kk) * N + n0);
        }
    };

    // ---- store registers into permuted smem buffer `buf` ----
    auto store_tile = [&](int buf) {
#pragma unroll
        for (int l = 0; l < 2; ++l) {
            int f4 = l * 256 + tid;
            // A element (r, c): fragment owner for m16n8k8 A-operand
            int r = f4 >> 2, c0 = (f4 & 3) * 4;
            int mi = r >> 4, rr = r & 15;
            float va[4] = {ra[l].x, ra[l].y, ra[l].z, ra[l].w};
#pragma unroll
            for (int q = 0; q < 4; ++q) {
                int c = c0 + q, ks = c >> 3, cc = c & 7;
                int j = (rr >> 3) + ((cc >> 2) << 1);
                int t = (rr & 7) * 4 + (cc & 3);
                As[buf][((ks * 8 + mi) * 32 + t) * 4 + j] = cvt_tf32(va[q]);
            }
            // B element (kk, n): fragment owner for B-operand
            int kk = f4 >> 5, n0 = (f4 & 31) * 4;
            int ks = kk >> 3, krem = kk & 7;
            int tig = krem & 3, jb = krem >> 2;
            float vb[4] = {rb[l].x, rb[l].y, rb[l].z, rb[l].w};
#pragma unroll
            for (int q = 0; q < 4; ++q) {
                int n = n0 + q, ni = n >> 3, g = n & 7;
                int t = g * 4 + tig;
                Bs[buf][((ks * 16 + ni) * 32 + t) * 2 + jb] = cvt_tf32(vb[q]);
            }
        }
    };

    // ---- compute on smem buffer p ----
    auto compute = [&](int p) {
#pragma unroll
        for (int ks = 0; ks < 2; ++ks) {
            unsigned int af[4][4];
            unsigned int bf[4][2];
#pragma unroll
            for (int mil = 0; mil < 4; ++mil) {
                float4 v = *(const float4*)&As[p][((ks * 8 + wm * 4 + mil) * 32 + lane) * 4];
                af[mil][0] = __float_as_uint(v.x);
                af[mil][1] = __float_as_uint(v.y);
                af[mil][2] = __float_as_uint(v.z);
                af[mil][3] = __float_as_uint(v.w);
            }
#pragma unroll
            for (int nil = 0; nil < 4; ++nil) {
                float2 v = *(const float2*)&Bs[p][((ks * 16 + wn * 4 + nil) * 32 + lane) * 2];
                bf[nil][0] = __float_as_uint(v.x);
                bf[nil][1] = __float_as_uint(v.y);
            }
#pragma unroll
            for (int mil = 0; mil < 4; ++mil)
#pragma unroll
                for (int nil = 0; nil < 4; ++nil) {
                    asm volatile(
                        "mma.sync.aligned.m16n8k8.row.col.f32.tf32.tf32.f32 "
                        "{%0,%1,%2,%3}, {%4,%5,%6,%7}, {%8,%9}, {%0,%1,%2,%3};"
                        : "+f"(acc[mil][nil][0]), "+f"(acc[mil][nil][1]),
                          "+f"(acc[mil][nil][2]), "+f"(acc[mil][nil][3])
                        : "r"(af[mil][0]), "r"(af[mil][1]),
                          "r"(af[mil][2]), "r"(af[mil][3]),
                          "r"(bf[nil][0]), "r"(bf[nil][1]));
                }
        }
    };

    // ---- pipelined main loop ----
    load_tile(0);
    store_tile(0);
    __syncthreads();
    for (int kt = 0; kt < nk; ++kt) {
        int p = kt & 1;
        if (kt + 1 < nk) load_tile(kt + 1);
        compute(p);
        if (kt + 1 < nk) store_tile(1 - p);
        __syncthreads();
    }

    // ---- epilogue: bias + store ----
    const int g = lane >> 2, tig = lane & 3;
#pragma unroll
    for (int mil = 0; mil < 4; ++mil) {
#pragma unroll
        for (int nil = 0; nil < 4; ++nil) {
            int row0 = brow * 128 + wm * 64 + mil * 16 + g;
            int col  = bcol * 128 + wn * 32 + nil * 8 + tig * 2;
            float b0 = bias[col], b1 = bias[col + 1];
            float2 v0 = make_float2(acc[mil][nil][0] + b0, acc[mil][nil][1] + b1);
            float2 v1 = make_float2(acc[mil][nil][2] + b0, acc[mil][nil][3] + b1);
            *(float2*)(C + (size_t)row0 * N + col) = v0;
            *(float2*)(C + (size_t)(row0 + 8) * N + col) = v1;
        }
    }
}

// ---------------------------------------------------------------------------
// RoPE + split + head-mean.  One block per (b,s), 128 threads (= dim d).
// RoPE is linear with per-position coefficients shared across heads, so
// rope(mean_h(k)) == mean_h(rope(k)).
// ---------------------------------------------------------------------------
__global__ __launch_bounds__(128)
void rope_split_mean_kernel(const float* __restrict__ qkv,
                            float* __restrict__ qout,
                            float* __restrict__ km,
                            float* __restrict__ vm)
{
    int bs = blockIdx.x;                 // 0..4095
    int b = bs >> 11, s = bs & 2047;
    int d = threadIdx.x;                 // 0..127
    const float* base = qkv + (size_t)bs * 6144;

    float c = 1.f, sn = 0.f;
    float sgn = (d < 16) ? -1.f : 1.f;
    if (d < 32) {
        float invf = (float)exp2(-(double)(d & 15) / 16.0 * log2(10000.0));
        float ang = (float)s * invf;     // fp32 multiply matches reference
        c = (float)cos((double)ang);
        sn = (float)sin((double)ang);
    }

    float ks = 0.f, vs = 0.f;
#pragma unroll
    for (int h = 0; h < 16; ++h) {
        ks += base[h * 384 + 128 + d];
        vs += base[h * 384 + 256 + d];
    }
    ks *= 0.0625f; vs *= 0.0625f;

    float kp = __shfl_xor_sync(0xffffffffu, ks, 16);  // rope partner (d ^ 16)
    if (d < 32) ks = ks * c + sgn * kp * sn;
    km[(size_t)bs * 128 + d] = ks;
    vm[(size_t)bs * 128 + d] = vs;

#pragma unroll
    for (int h = 0; h < 16; ++h) {
        float qv = base[h * 384 + d];
        float qp = __shfl_xor_sync(0xffffffffu, qv, 16);
        float qr = (d < 32) ? (qv * c + sgn * qp * sn) : qv;
        qout[(((size_t)(b * 16 + h)) * SS + s) * 128 + d] = qr;
    }
}

// ---------------------------------------------------------------------------
// Attention. One block per (b, qpos); 256 threads; all 16 heads share K/V.
// ---------------------------------------------------------------------------
#define ATTN_SMEM_FLOATS (16*128 + 16*320 + 64*129 + 320 + 320)

__global__ __launch_bounds__(256)
void attn_kernel(const float* __restrict__ q,
                 const float* __restrict__ km,
                 const float* __restrict__ vm,
                 const float* __restrict__ mask,
                 const int* __restrict__ gidx,
                 float* __restrict__ out)
{
    extern __shared__ float sm[];
    float* qs = sm;                       // 2048
    float* sc = sm + 2048;                // 5120
    float* kt = sm + 2048 + 5120;         // 64*129 = 8256
    float* kadd = kt + 64 * 129;          // 320
    int* kpos = (int*)(kadd + 320);       // 320

    const int bq = blockIdx.x;
    const int b = bq >> 11;
    const int qp = bq & 2047;
    const int tid = threadIdx.x;

    {
        int h = tid >> 4, d0 = (tid & 15) * 8;
        const float* src = q + (((size_t)(b * 16 + h)) * SS + qp) * 128 + d0;
        *(float4*)(qs + h * 128 + d0)     = *(const float4*)src;
        *(float4*)(qs + h * 128 + d0 + 4) = *(const float4*)(src + 4);
    }

    int ng, nw, wstart, tstep;
    if (qp < WIN) { ng = 0; nw = qp + 1; wstart = 0; tstep = -1; }
    else { ng = GG; nw = WIN; tstep = qp - WIN; wstart = tstep + 1; }
    const int nk = ng + nw;
    const int nchunk = (nk + 63) >> 6;

    const float scale = 0.08838834764831845f;  // 1/sqrt(128)
    const float NEG = -1e30f;

    // ---- K phase ----
    for (int c = 0; c < nchunk; ++c) {
        int cb = c << 6;
        __syncthreads();
        if (tid < 64) {
            int jk = cb + tid;
            int pos = 0; float add = NEG;
            if (jk < nk) {
                if (jk < ng) {
                    pos = gidx[b * 64 + jk];
                    add = (pos < tstep) ? 0.f : NEG;
                } else {
                    pos = wstart + (jk - ng);
                    add = mask[b * SS + pos];
                }
            }
            kpos[jk] = pos;
            kadd[jk] = add;
        }
        __syncthreads();
        {
            int row = tid >> 2, q4 = tid & 3;
            int pos = kpos[cb + row];
            const float* src = km + ((size_t)b * SS + pos) * 128;
            float* dstrow = kt + row * 129;
#pragma unroll
            for (int i = 0; i < 8; ++i) {
                int off = (q4 + (i << 2)) * 4;
                float4 v = *(const float4*)(src + off);
                dstrow[off + 0] = v.x; dstrow[off + 1] = v.y;
                dstrow[off + 2] = v.z; dstrow[off + 3] = v.w;
            }
        }
        __syncthreads();
        {
            int h0 = (tid >> 5) << 1;
            int j0 = tid & 31, j1 = j0 + 32;
            float s00 = 0, s01 = 0, s10 = 0, s11 = 0;
            const float* qa = qs + h0 * 128;
            const float* qb = qa + 128;
            const float* k0 = kt + j0 * 129;
            const float* k1 = kt + j1 * 129;
#pragma unroll 4
            for (int d = 0; d < 128; ++d) {
                float a0 = qa[d], a1 = qb[d];
                float b0 = k0[d], b1 = k1[d];
                s00 += a0 * b0; s01 += a0 * b1;
                s10 += a1 * b0; s11 += a1 * b1;
            }
            float ad0 = kadd[cb + j0], ad1 = kadd[cb + j1];
            sc[h0 * 320 + cb + j0] = s00 * scale + ad0;
            sc[h0 * 320 + cb + j1] = s01 * scale + ad1;
            sc[(h0 + 1) * 320 + cb + j0] = s10 * scale + ad0;
            sc[(h0 + 1) * 320 + cb + j1] = s11 * scale + ad1;
        }
    }
    __syncthreads();

    // ---- softmax ----
    {
        int w = tid >> 5, lane = tid & 31;
        int ntot = nchunk << 6;
        for (int hh = 0; hh < 2; ++hh) {
            float* row = sc + (w * 2 + hh) * 320;
            float m = -3.4e38f;
            for (int j = lane; j < ntot; j += 32) m = fmaxf(m, row[j]);
#pragma unroll
            for (int o = 16; o > 0; o >>= 1) m = fmaxf(m, __shfl_xor_sync(0xffffffffu, m, o));
            float sum = 0.f;
            for (int j = lane; j < ntot; j += 32) {
                float e = __expf(row[j] - m);
                row[j] = e; sum += e;
            }
#pragma unroll
            for (int o = 16; o > 0; o >>= 1) sum += __shfl_xor_sync(0xffffffffu, sum, o);
            float inv = 1.f / sum;
            for (int j = lane; j < ntot; j += 32) row[j] *= inv;
        }
    }

    // ---- V phase ----
    float acc[8] = {0, 0, 0, 0, 0, 0, 0, 0};
    const int h = tid >> 4, dl = tid & 15;
    for (int c = 0; c < nchunk; ++c) {
        int cb = c << 6;
        __syncthreads();
        {
            int row = tid >> 2, q4 = tid & 3;
            int pos = kpos[cb + row];
            const float* src = vm + ((size_t)b * SS + pos) * 128;
            float* dstrow = kt + row * 129;
#pragma unroll
            for (int i = 0; i < 8; ++i) {
                int off = (q4 + (i << 2)) * 4;
                float4 v = *(const float4*)(src + off);
                dstrow[off + 0] = v.x; dstrow[off + 1] = v.y;
                dstrow[off + 2] = v.z; dstrow[off + 3] = v.w;
            }
        }
        __syncthreads();
        const float* wrow = sc + h * 320 + cb;
#pragma unroll 2
        for (int j = 0; j < 64; ++j) {
            float wv = wrow[j];
            const float* vr = kt + j * 129 + dl;
#pragma unroll
            for (int i = 0; i < 8; ++i) acc[i] += wv * vr[i * 16];
        }
    }

    float* o = out + ((size_t)b * SS + qp) * HD + h * 128 + dl;
#pragma unroll
    for (int i = 0; i < 8; ++i) o[i * 16] = acc[i];
}

// ---------------------------------------------------------------------------
extern "C" void kernel_launch(void* const* d_in, const int* in_sizes, int n_in,
                              void* d_out, int out_size)
{
    const float* hidden = (const float*)d_in[0];
    const float* mask   = (const float*)d_in[1];
    const int*   gidx   = (const int*)d_in[2];
    const float* Wqkv   = (const float*)d_in[3];
    const float* bqkv   = (const float*)d_in[4];
    const float* Wo     = (const float*)d_in[5];
    const float* bo     = (const float*)d_in[6];
    float* out = (float*)d_out;

    float *qkv, *qbuf, *kmp, *vmp, *attn;
    cudaGetSymbolAddress((void**)&qkv,  g_qkv);
    cudaGetSymbolAddress((void**)&qbuf, g_q);
    cudaGetSymbolAddress((void**)&kmp,  g_km);
    cudaGetSymbolAddress((void**)&vmp,  g_vm);
    cudaGetSymbolAddress((void**)&attn, g_attn);

    const int smem_attn = ATTN_SMEM_FLOATS * 4;
    cudaFuncSetAttribute(attn_kernel, cudaFuncAttributeMaxDynamicSharedMemorySize,
                         smem_attn);

    // 1) QKV GEMM: [4096,2048] @ [2048,6144] + b   (tf32 tensor cores)
    tf32_gemm_bias<<<dim3(6144 / 128, 4096 / 128), 256>>>(
        hidden, Wqkv, bqkv, qkv, 4096, 6144, 2048);

    // 2) RoPE + split + head-mean
    rope_split_mean_kernel<<<BB * SS, 128>>>(qkv, qbuf, kmp, vmp);

    // 3) Attention (all heads per block; K/V shared across heads)
    attn_kernel<<<BB * SS, 256, smem_attn>>>(qbuf, kmp, vmp, mask, gidx, attn);

    // 4) Output GEMM: [4096,2048] @ [2048,2048] + b   (tf32 tensor cores)
    tf32_gemm_bias<<<dim3(2048 / 128, 4096 / 128), 256>>>(
        attn, Wo, bo, out, 4096, 2048, 2048);
}

// round 4
// speedup vs baseline: 2.3594x; 2.3521x over previous
#include <cuda_runtime.h>
#include <cuda_bf16.h>
#include <cstdint>
#include <math.h>

// Problem constants
#define BB 2
#define SS 2048
#define HH 16
#define DD 128
#define HD 2048
#define WIN 256
#define GG 64

// Scratch (device globals: allocation-free rule)
__device__ float g_qkv[(size_t)BB * SS * 3 * HD];   // [B,S,6144]
__device__ float g_q[(size_t)BB * HH * SS * DD];    // [B,H,S,D] roped q
__device__ float g_km[(size_t)BB * SS * DD];        // k_mean (roped)
__device__ float g_vm[(size_t)BB * SS * DD];        // v_mean
__device__ float g_attn[(size_t)BB * SS * HD];      // [B,S,H*D] attention out

// ---------------------------------------------------------------------------
// TF32 tensor-core GEMM: C[M,N] = A[M,K] @ B[K,N] + bias, row-major fp32.
// 128x128 block tile, BK=16, 8 warps (each 64x32 via mma.sync.m16n8k8.tf32).
// cp.async (LDGSTS .cg, 16B) fills PLAIN smem layouts (A[m][k] stride 20,
// B[k][n] stride 132) in a 3-stage ring; fragments are gathered with
// conflict-free scalar LDS.32 (bank bijection via the odd strides);
// cvt.rna.tf32 applied on fragment registers. No STS anywhere.
// Requires M%128==0, N%128==0, K%16==0, K/16>=2.
// ---------------------------------------------------------------------------
#define ASTRIDE 20
#define BSTRIDE 132
#define A_STG (128 * ASTRIDE)            // 2560 floats
#define B_STG (16 * BSTRIDE)             // 2112 floats
#define STG_FLOATS (A_STG + B_STG)       // 4672 floats
#define GEMM_SMEM_BYTES (3 * STG_FLOATS * 4)   // 56064 B

__device__ __forceinline__ unsigned int cvt_tf32_bits(float v) {
    unsigned int t;
    asm("cvt.rna.tf32.f32 %0, %1;" : "=r"(t) : "f"(v));
    return t;
}

__global__ __launch_bounds__(256, 2)
void tf32_gemm_bias(const float* __restrict__ A, const float* __restrict__ B,
                    const float* __restrict__ bias, float* __restrict__ C,
                    int M, int N, int K)
{
    extern __shared__ float smem_g[];

    const int tid  = threadIdx.x;
    const int lane = tid & 31;
    const int warp = tid >> 5;
    const int wm = warp >> 2;       // 0..1  (m half)
    const int wn = warp & 3;        // 0..3  (n quarter)
    const int brow = blockIdx.y, bcol = blockIdx.x;

    const float* Ab = A + (size_t)brow * 128 * K;
    const float* Bb = B + (size_t)bcol * 128;

    const int nk = K >> 4;

    float acc[4][4][4];
#pragma unroll
    for (int i = 0; i < 4; i++)
#pragma unroll
        for (int j = 0; j < 4; j++)
#pragma unroll
            for (int r = 0; r < 4; r++) acc[i][j][r] = 0.f;

    // ---- async-copy one K-tile into ring stage kt%3 ----
    auto issue = [&](int kt) {
        int k0 = kt << 4;
        float* st = smem_g + (kt % 3) * STG_FLOATS;
#pragma unroll
        for (int l = 0; l < 2; ++l) {
            int ca = l * 256 + tid;                 // 0..511
            // A chunk: (m, k4..k4+3)
            int m = ca >> 2, k4 = (ca & 3) << 2;
            const float* srca = Ab + (size_t)m * K + k0 + k4;
            unsigned da = (unsigned)__cvta_generic_to_shared(st + m * ASTRIDE + k4);
            asm volatile("cp.async.cg.shared.global [%0], [%1], 16;\n"
                         :: "r"(da), "l"(srca));
            // B chunk: (k, n4..n4+3)
            int kk = ca >> 5, n4 = (ca & 31) << 2;
            const float* srcb = Bb + (size_t)(k0 + kk) * N + n4;
            unsigned db = (unsigned)__cvta_generic_to_shared(st + A_STG + kk * BSTRIDE + n4);
            asm volatile("cp.async.cg.shared.global [%0], [%1], 16;\n"
                         :: "r"(db), "l"(srcb));
        }
    };

    const int g = lane >> 2, c = lane & 3;

    auto compute = [&](int s) {
        const float* Ast = smem_g + s * STG_FLOATS;
        const float* Bst = Ast + A_STG;
#pragma unroll
        for (int ks = 0; ks < 2; ++ks) {
            int kb = ks * 8;
            unsigned int af[4][4];
            unsigned int bf[4][2];
#pragma unroll
            for (int mil = 0; mil < 4; ++mil) {
                const float* pa = Ast + (wm * 64 + mil * 16 + g) * ASTRIDE + kb + c;
                af[mil][0] = cvt_tf32_bits(pa[0]);
                af[mil][1] = cvt_tf32_bits(pa[8 * ASTRIDE]);
                af[mil][2] = cvt_tf32_bits(pa[4]);
                af[mil][3] = cvt_tf32_bits(pa[8 * ASTRIDE + 4]);
            }
#pragma unroll
            for (int nil = 0; nil < 4; ++nil) {
                const float* pb = Bst + (kb + c) * BSTRIDE + wn * 32 + nil * 8 + g;
                bf[nil][0] = cvt_tf32_bits(pb[0]);
                bf[nil][1] = cvt_tf32_bits(pb[4 * BSTRIDE]);
            }
#pragma unroll
            for (int mil = 0; mil < 4; ++mil)
#pragma unroll
                for (int nil = 0; nil < 4; ++nil) {
                    asm volatile(
                        "mma.sync.aligned.m16n8k8.row.col.f32.tf32.tf32.f32 "
                        "{%0,%1,%2,%3}, {%4,%5,%6,%7}, {%8,%9}, {%0,%1,%2,%3};"
                        : "+f"(acc[mil][nil][0]), "+f"(acc[mil][nil][1]),
                          "+f"(acc[mil][nil][2]), "+f"(acc[mil][nil][3])
                        : "r"(af[mil][0]), "r"(af[mil][1]),
                          "r"(af[mil][2]), "r"(af[mil][3]),
                          "r"(bf[nil][0]), "r"(bf[nil][1]));
                }
        }
    };

    // ---- 3-stage pipeline ----
    issue(0);
    asm volatile("cp.async.commit_group;");
    issue(1);
    asm volatile("cp.async.commit_group;");

    for (int kt = 0; kt < nk; ++kt) {
        if (kt + 2 < nk) issue(kt + 2);
        asm volatile("cp.async.commit_group;");     // possibly-empty group
        asm volatile("cp.async.wait_group 2;");     // stage kt drained
        __syncthreads();
        compute(kt % 3);
        __syncthreads();
    }

    // ---- epilogue: bias + store ----
    const int tig = lane & 3;
#pragma unroll
    for (int mil = 0; mil < 4; ++mil) {
#pragma unroll
        for (int nil = 0; nil < 4; ++nil) {
            int row0 = brow * 128 + wm * 64 + mil * 16 + g;
            int col  = bcol * 128 + wn * 32 + nil * 8 + tig * 2;
            float b0 = bias[col], b1 = bias[col + 1];
            float2 v0 = make_float2(acc[mil][nil][0] + b0, acc[mil][nil][1] + b1);
            float2 v1 = make_float2(acc[mil][nil][2] + b0, acc[mil][nil][3] + b1);
            *(float2*)(C + (size_t)row0 * N + col) = v0;
            *(float2*)(C + (size_t)(row0 + 8) * N + col) = v1;
        }
    }
}

// ---------------------------------------------------------------------------
// RoPE + split + head-mean.  One block per (b,s), 128 threads (= dim d).
// RoPE is linear with per-position coefficients shared across heads, so
// rope(mean_h(k)) == mean_h(rope(k)).
// ---------------------------------------------------------------------------
__global__ __launch_bounds__(128)
void rope_split_mean_kernel(const float* __restrict__ qkv,
                            float* __restrict__ qout,
                            float* __restrict__ km,
                            float* __restrict__ vm)
{
    int bs = blockIdx.x;                 // 0..4095
    int b = bs >> 11, s = bs & 2047;
    int d = threadIdx.x;                 // 0..127
    const float* base = qkv + (size_t)bs * 6144;

    float c = 1.f, sn = 0.f;
    float sgn = (d < 16) ? -1.f : 1.f;
    if (d < 32) {
        float invf = (float)exp2(-(double)(d & 15) / 16.0 * log2(10000.0));
        float ang = (float)s * invf;     // fp32 multiply matches reference
        c = (float)cos((double)ang);
        sn = (float)sin((double)ang);
    }

    float ks = 0.f, vs = 0.f;
#pragma unroll
    for (int h = 0; h < 16; ++h) {
        ks += base[h * 384 + 128 + d];
        vs += base[h * 384 + 256 + d];
    }
    ks *= 0.0625f; vs *= 0.0625f;

    float kp = __shfl_xor_sync(0xffffffffu, ks, 16);  // rope partner (d ^ 16)
    if (d < 32) ks = ks * c + sgn * kp * sn;
    km[(size_t)bs * 128 + d] = ks;
    vm[(size_t)bs * 128 + d] = vs;

#pragma unroll
    for (int h = 0; h < 16; ++h) {
        float qv = base[h * 384 + d];
        float qp = __shfl_xor_sync(0xffffffffu, qv, 16);
        float qr = (d < 32) ? (qv * c + sgn * qp * sn) : qv;
        qout[(((size_t)(b * 16 + h)) * SS + s) * 128 + d] = qr;
    }
}

// ---------------------------------------------------------------------------
// Attention. One block per (b, qpos); 256 threads; all 16 heads share K/V.
// ---------------------------------------------------------------------------
#define ATTN_SMEM_FLOATS (16*128 + 16*320 + 64*129 + 320 + 320)

__global__ __launch_bounds__(256)
void attn_kernel(const float* __restrict__ q,
                 const float* __restrict__ km,
                 const float* __restrict__ vm,
                 const float* __restrict__ mask,
                 const int* __restrict__ gidx,
                 float* __restrict__ out)
{
    extern __shared__ float sm[];
    float* qs = sm;                       // 2048
    float* sc = sm + 2048;                // 5120
    float* kt = sm + 2048 + 5120;         // 64*129 = 8256
    float* kadd = kt + 64 * 129;          // 320
    int* kpos = (int*)(kadd + 320);       // 320

    const int bq = blockIdx.x;
    const int b = bq >> 11;
    const int qp = bq & 2047;
    const int tid = threadIdx.x;

    {
        int h = tid >> 4, d0 = (tid & 15) * 8;
        const float* src = q + (((size_t)(b * 16 + h)) * SS + qp) * 128 + d0;
        *(float4*)(qs + h * 128 + d0)     = *(const float4*)src;
        *(float4*)(qs + h * 128 + d0 + 4) = *(const float4*)(src + 4);
    }

    int ng, nw, wstart, tstep;
    if (qp < WIN) { ng = 0; nw = qp + 1; wstart = 0; tstep = -1; }
    else { ng = GG; nw = WIN; tstep = qp - WIN; wstart = tstep + 1; }
    const int nk = ng + nw;
    const int nchunk = (nk + 63) >> 6;

    const float scale = 0.08838834764831845f;  // 1/sqrt(128)
    const float NEG = -1e30f;

    // ---- K phase ----
    for (int c = 0; c < nchunk; ++c) {
        int cb = c << 6;
        __syncthreads();
        if (tid < 64) {
            int jk = cb + tid;
            int pos = 0; float add = NEG;
            if (jk < nk) {
                if (jk < ng) {
                    pos = gidx[b * 64 + jk];
                    add = (pos < tstep) ? 0.f : NEG;
                } else {
                    pos = wstart + (jk - ng);
                    add = mask[b * SS + pos];
                }
            }
            kpos[jk] = pos;
            kadd[jk] = add;
        }
        __syncthreads();
        {
            int row = tid >> 2, q4 = tid & 3;
            int pos = kpos[cb + row];
            const float* src = km + ((size_t)b * SS + pos) * 128;
            float* dstrow = kt + row * 129;
#pragma unroll
            for (int i = 0; i < 8; ++i) {
                int off = (q4 + (i << 2)) * 4;
                float4 v = *(const float4*)(src + off);
                dstrow[off + 0] = v.x; dstrow[off + 1] = v.y;
                dstrow[off + 2] = v.z; dstrow[off + 3] = v.w;
            }
        }
        __syncthreads();
        {
            int h0 = (tid >> 5) << 1;
            int j0 = tid & 31, j1 = j0 + 32;
            float s00 = 0, s01 = 0, s10 = 0, s11 = 0;
            const float* qa = qs + h0 * 128;
            const float* qb = qa + 128;
            const float* k0 = kt + j0 * 129;
            const float* k1 = kt + j1 * 129;
#pragma unroll 4
            for (int d = 0; d < 128; ++d) {
                float a0 = qa[d], a1 = qb[d];
                float b0 = k0[d], b1 = k1[d];
                s00 += a0 * b0; s01 += a0 * b1;
                s10 += a1 * b0; s11 += a1 * b1;
            }
            float ad0 = kadd[cb + j0], ad1 = kadd[cb + j1];
            sc[h0 * 320 + cb + j0] = s00 * scale + ad0;
            sc[h0 * 320 + cb + j1] = s01 * scale + ad1;
            sc[(h0 + 1) * 320 + cb + j0] = s10 * scale + ad0;
            sc[(h0 + 1) * 320 + cb + j1] = s11 * scale + ad1;
        }
    }
    __syncthreads();

    // ---- softmax ----
    {
        int w = tid >> 5, lane = tid & 31;
        int ntot = nchunk << 6;
        for (int hh = 0; hh < 2; ++hh) {
            float* row = sc + (w * 2 + hh) * 320;
            float m = -3.4e38f;
            for (int j = lane; j < ntot; j += 32) m = fmaxf(m, row[j]);
#pragma unroll
            for (int o = 16; o > 0; o >>= 1) m = fmaxf(m, __shfl_xor_sync(0xffffffffu, m, o));
            float sum = 0.f;
            for (int j = lane; j < ntot; j += 32) {
                float e = __expf(row[j] - m);
                row[j] = e; sum += e;
            }
#pragma unroll
            for (int o = 16; o > 0; o >>= 1) sum += __shfl_xor_sync(0xffffffffu, sum, o);
            float inv = 1.f / sum;
            for (int j = lane; j < ntot; j += 32) row[j] *= inv;
        }
    }

    // ---- V phase ----
    float acc[8] = {0, 0, 0, 0, 0, 0, 0, 0};
    const int h = tid >> 4, dl = tid & 15;
    for (int c = 0; c < nchunk; ++c) {
        int cb = c << 6;
        __syncthreads();
        {
            int row = tid >> 2, q4 = tid & 3;
            int pos = kpos[cb + row];
            const float* src = vm + ((size_t)b * SS + pos) * 128;
            float* dstrow = kt + row * 129;
#pragma unroll
            for (int i = 0; i < 8; ++i) {
                int off = (q4 + (i << 2)) * 4;
                float4 v = *(const float4*)(src + off);
                dstrow[off + 0] = v.x; dstrow[off + 1] = v.y;
                dstrow[off + 2] = v.z; dstrow[off + 3] = v.w;
            }
        }
        __syncthreads();
        const float* wrow = sc + h * 320 + cb;
#pragma unroll 2
        for (int j = 0; j < 64; ++j) {
            float wv = wrow[j];
            const float* vr = kt + j * 129 + dl;
#pragma unroll
            for (int i = 0; i < 8; ++i) acc[i] += wv * vr[i * 16];
        }
    }

    float* o = out + ((size_t)b * SS + qp) * HD + h * 128 + dl;
#pragma unroll
    for (int i = 0; i < 8; ++i) o[i * 16] = acc[i];
}

// ---------------------------------------------------------------------------
extern "C" void kernel_launch(void* const* d_in, const int* in_sizes, int n_in,
                              void* d_out, int out_size)
{
    const float* hidden = (const float*)d_in[0];
    const float* mask   = (const float*)d_in[1];
    const int*   gidx   = (const int*)d_in[2];
    const float* Wqkv   = (const float*)d_in[3];
    const float* bqkv   = (const float*)d_in[4];
    const float* Wo     = (const float*)d_in[5];
    const float* bo     = (const float*)d_in[6];
    float* out = (float*)d_out;

    float *qkv, *qbuf, *kmp, *vmp, *attn;
    cudaGetSymbolAddress((void**)&qkv,  g_qkv);
    cudaGetSymbolAddress((void**)&qbuf, g_q);
    cudaGetSymbolAddress((void**)&kmp,  g_km);
    cudaGetSymbolAddress((void**)&vmp,  g_vm);
    cudaGetSymbolAddress((void**)&attn, g_attn);

    const int smem_attn = ATTN_SMEM_FLOATS * 4;
    cudaFuncSetAttribute(attn_kernel, cudaFuncAttributeMaxDynamicSharedMemorySize,
                         smem_attn);
    cudaFuncSetAttribute(tf32_gemm_bias, cudaFuncAttributeMaxDynamicSharedMemorySize,
                         GEMM_SMEM_BYTES);

    // 1) QKV GEMM: [4096,2048] @ [2048,6144] + b   (tf32 tensor cores)
    tf32_gemm_bias<<<dim3(6144 / 128, 4096 / 128), 256, GEMM_SMEM_BYTES>>>(
        hidden, Wqkv, bqkv, qkv, 4096, 6144, 2048);

    // 2) RoPE + split + head-mean
    rope_split_mean_kernel<<<BB * SS, 128>>>(qkv, qbuf, kmp, vmp);

    // 3) Attention (all heads per block; K/V shared across heads)
    attn_kernel<<<BB * SS, 256, smem_attn>>>(qbuf, kmp, vmp, mask, gidx, attn);

    // 4) Output GEMM: [4096,2048] @ [2048,2048] + b   (tf32 tensor cores)
    tf32_gemm_bias<<<dim3(2048 / 128, 4096 / 128), 256, GEMM_SMEM_BYTES>>>(
        attn, Wo, bo, out, 4096, 2048, 2048);
}

// round 5
// speedup vs baseline: 2.3941x; 1.0147x over previous
#include <cuda_runtime.h>
#include <cuda_bf16.h>
#include <cstdint>
#include <math.h>

// Problem constants
#define BB 2
#define SS 2048
#define HH 16
#define DD 128
#define HD 2048
#define WIN 256
#define GG 64

// Scratch (device globals: allocation-free rule)
__device__ float g_qkv[(size_t)BB * SS * 3 * HD];   // [B,S,6144]
__device__ float g_q[(size_t)BB * HH * SS * DD];    // [B,H,S,D] roped q
__device__ float g_km[(size_t)BB * SS * DD];        // k_mean (roped)
__device__ float g_vm[(size_t)BB * SS * DD];        // v_mean
__device__ float g_attn[(size_t)BB * SS * HD];      // [B,S,H*D] attn out (tf32-rounded)
// tf32-preconverted GEMM operands
__device__ float g_hid_t[(size_t)BB * SS * HD];     // hidden, tf32
__device__ float g_wqkv_t[(size_t)HD * 3 * HD];     // W_qkv, tf32
__device__ float g_wo_t[(size_t)HD * HD];           // W_o, tf32

__device__ __forceinline__ unsigned int cvt_tf32_bits(float v) {
    unsigned int t;
    asm("cvt.rna.tf32.f32 %0, %1;" : "=r"(t) : "f"(v));
    return t;
}
__device__ __forceinline__ float cvt_tf32(float v) {
    return __uint_as_float(cvt_tf32_bits(v));
}

// ---------------------------------------------------------------------------
// Elementwise tf32 rounding (float4 vectorized). n4 = n/4.
// ---------------------------------------------------------------------------
__global__ __launch_bounds__(512)
void cvt_tf32_vec(const float4* __restrict__ in, float4* __restrict__ out, int n4)
{
    int i = blockIdx.x * blockDim.x + threadIdx.x;
    if (i < n4) {
        float4 v = in[i];
        v.x = cvt_tf32(v.x); v.y = cvt_tf32(v.y);
        v.z = cvt_tf32(v.z); v.w = cvt_tf32(v.w);
        out[i] = v;
    }
}

// ---------------------------------------------------------------------------
// TF32 tensor-core GEMM: C[M,N] = A[M,K] @ B[K,N] + bias, row-major.
// A and B must already hold tf32-rounded values. 128x128 block tile, BK=16,
// 8 warps (each 64x32 via mma.sync.m16n8k8.tf32). cp.async 16B fills plain
// layouts (A[m][k] stride 20, B[k][n] stride 132) in a 4-stage ring with ONE
// __syncthreads per K-tile; conflict-free scalar LDS gathers (bank bijection
// via odd strides). No STS, no cvt in the mainloop.
// Requires M%128==0, N%128==0, K%16==0, K/16>=3.
// ---------------------------------------------------------------------------
#define ASTRIDE 20
#define BSTRIDE 132
#define A_STG (128 * ASTRIDE)            // 2560 floats
#define B_STG (16 * BSTRIDE)             // 2112 floats
#define STG_FLOATS (A_STG + B_STG)       // 4672 floats
#define NSTAGE 4
#define GEMM_SMEM_BYTES (NSTAGE * STG_FLOATS * 4)   // 74752 B

__global__ __launch_bounds__(256, 2)
void tf32_gemm_bias(const float* __restrict__ A, const float* __restrict__ B,
                    const float* __restrict__ bias, float* __restrict__ C,
                    int M, int N, int K)
{
    extern __shared__ float smem_g[];

    const int tid  = threadIdx.x;
    const int lane = tid & 31;
    const int warp = tid >> 5;
    const int wm = warp >> 2;       // 0..1  (m half)
    const int wn = warp & 3;        // 0..3  (n quarter)
    const int brow = blockIdx.y, bcol = blockIdx.x;

    const float* Ab = A + (size_t)brow * 128 * K;
    const float* Bb = B + (size_t)bcol * 128;

    const int nk = K >> 4;

    float acc[4][4][4];
#pragma unroll
    for (int i = 0; i < 4; i++)
#pragma unroll
        for (int j = 0; j < 4; j++)
#pragma unroll
            for (int r = 0; r < 4; r++) acc[i][j][r] = 0.f;

    // ---- async-copy one K-tile into ring stage kt%NSTAGE ----
    auto issue = [&](int kt) {
        int k0 = kt << 4;
        float* st = smem_g + (kt % NSTAGE) * STG_FLOATS;
#pragma unroll
        for (int l = 0; l < 2; ++l) {
            int ca = l * 256 + tid;                 // 0..511
            int m = ca >> 2, k4 = (ca & 3) << 2;
            const float* srca = Ab + (size_t)m * K + k0 + k4;
            unsigned da = (unsigned)__cvta_generic_to_shared(st + m * ASTRIDE + k4);
            asm volatile("cp.async.cg.shared.global [%0], [%1], 16;\n"
                         :: "r"(da), "l"(srca));
            int kk = ca >> 5, n4 = (ca & 31) << 2;
            const float* srcb = Bb + (size_t)(k0 + kk) * N + n4;
            unsigned db = (unsigned)__cvta_generic_to_shared(st + A_STG + kk * BSTRIDE + n4);
            asm volatile("cp.async.cg.shared.global [%0], [%1], 16;\n"
                         :: "r"(db), "l"(srcb));
        }
    };

    const int g = lane >> 2, c = lane & 3;
    const int a_base = (wm * 64 + g) * ASTRIDE + c;
    const int b_base = c * BSTRIDE + wn * 32 + g;

    auto compute = [&](int s) {
        const float* Ast = smem_g + s * STG_FLOATS;
        const float* Bst = Ast + A_STG;
#pragma unroll
        for (int ks = 0; ks < 2; ++ks) {
            int kb = ks * 8;
            unsigned int af[4][4];
            unsigned int bf[4][2];
#pragma unroll
            for (int mil = 0; mil < 4; ++mil) {
                const float* pa = Ast + a_base + mil * (16 * ASTRIDE) + kb;
                af[mil][0] = __float_as_uint(pa[0]);
                af[mil][1] = __float_as_uint(pa[8 * ASTRIDE]);
                af[mil][2] = __float_as_uint(pa[4]);
                af[mil][3] = __float_as_uint(pa[8 * ASTRIDE + 4]);
            }
#pragma unroll
            for (int nil = 0; nil < 4; ++nil) {
                const float* pb = Bst + b_base + kb * BSTRIDE + nil * 8;
                bf[nil][0] = __float_as_uint(pb[0]);
                bf[nil][1] = __float_as_uint(pb[4 * BSTRIDE]);
            }
#pragma unroll
            for (int mil = 0; mil < 4; ++mil)
#pragma unroll
                for (int nil = 0; nil < 4; ++nil) {
                    asm volatile(
                        "mma.sync.aligned.m16n8k8.row.col.f32.tf32.tf32.f32 "
                        "{%0,%1,%2,%3}, {%4,%5,%6,%7}, {%8,%9}, {%0,%1,%2,%3};"
                        : "+f"(acc[mil][nil][0]), "+f"(acc[mil][nil][1]),
                          "+f"(acc[mil][nil][2]), "+f"(acc[mil][nil][3])
                        : "r"(af[mil][0]), "r"(af[mil][1]),
                          "r"(af[mil][2]), "r"(af[mil][3]),
                          "r"(bf[nil][0]), "r"(bf[nil][1]));
                }
        }
    };

    // ---- 4-stage pipeline, one barrier per tile ----
    issue(0);
    asm volatile("cp.async.commit_group;");
    issue(1);
    asm volatile("cp.async.commit_group;");
    issue(2);
    asm volatile("cp.async.commit_group;");

    for (int kt = 0; kt < nk; ++kt) {
        asm volatile("cp.async.wait_group 2;");     // group kt complete
        __syncthreads();                            // all threads' stage kt done
        compute(kt % NSTAGE);
        if (kt + 3 < nk) issue(kt + 3);
        asm volatile("cp.async.commit_group;");     // possibly empty
    }

    // ---- epilogue: bias + store ----
    const int tig = lane & 3;
#pragma unroll
    for (int mil = 0; mil < 4; ++mil) {
#pragma unroll
        for (int nil = 0; nil < 4; ++nil) {
            int row0 = brow * 128 + wm * 64 + mil * 16 + g;
            int col  = bcol * 128 + wn * 32 + nil * 8 + tig * 2;
            float b0 = bias[col], b1 = bias[col + 1];
            float2 v0 = make_float2(acc[mil][nil][0] + b0, acc[mil][nil][1] + b1);
            float2 v1 = make_float2(acc[mil][nil][2] + b0, acc[mil][nil][3] + b1);
            *(float2*)(C + (size_t)row0 * N + col) = v0;
            *(float2*)(C + (size_t)(row0 + 8) * N + col) = v1;
        }
    }
}

// ---------------------------------------------------------------------------
// RoPE + split + head-mean.  One block per (b,s), 128 threads (= dim d).
// ---------------------------------------------------------------------------
__global__ __launch_bounds__(128)
void rope_split_mean_kernel(const float* __restrict__ qkv,
                            float* __restrict__ qout,
                            float* __restrict__ km,
                            float* __restrict__ vm)
{
    int bs = blockIdx.x;                 // 0..4095
    int b = bs >> 11, s = bs & 2047;
    int d = threadIdx.x;                 // 0..127
    const float* base = qkv + (size_t)bs * 6144;

    float c = 1.f, sn = 0.f;
    float sgn = (d < 16) ? -1.f : 1.f;
    if (d < 32) {
        float invf = (float)exp2(-(double)(d & 15) / 16.0 * log2(10000.0));
        float ang = (float)s * invf;     // fp32 multiply matches reference
        c = (float)cos((double)ang);
        sn = (float)sin((double)ang);
    }

    float ks = 0.f, vs = 0.f;
#pragma unroll
    for (int h = 0; h < 16; ++h) {
        ks += base[h * 384 + 128 + d];
        vs += base[h * 384 + 256 + d];
    }
    ks *= 0.0625f; vs *= 0.0625f;

    float kp = __shfl_xor_sync(0xffffffffu, ks, 16);  // rope partner (d ^ 16)
    if (d < 32) ks = ks * c + sgn * kp * sn;
    km[(size_t)bs * 128 + d] = ks;
    vm[(size_t)bs * 128 + d] = vs;

#pragma unroll
    for (int h = 0; h < 16; ++h) {
        float qv = base[h * 384 + d];
        float qp = __shfl_xor_sync(0xffffffffu, qv, 16);
        float qr = (d < 32) ? (qv * c + sgn * qp * sn) : qv;
        qout[(((size_t)(b * 16 + h)) * SS + s) * 128 + d] = qr;
    }
}

// ---------------------------------------------------------------------------
// Attention. One block per (b, qpos); 256 threads; all 16 heads share K/V.
// Output written tf32-rounded (it is the A-operand of the final GEMM).
// ---------------------------------------------------------------------------
#define ATTN_SMEM_FLOATS (16*128 + 16*320 + 64*129 + 320 + 320)

__global__ __launch_bounds__(256)
void attn_kernel(const float* __restrict__ q,
                 const float* __restrict__ km,
                 const float* __restrict__ vm,
                 const float* __restrict__ mask,
                 const int* __restrict__ gidx,
                 float* __restrict__ out)
{
    extern __shared__ float sm[];
    float* qs = sm;                       // 2048
    float* sc = sm + 2048;                // 5120
    float* kt = sm + 2048 + 5120;         // 64*129 = 8256
    float* kadd = kt + 64 * 129;          // 320
    int* kpos = (int*)(kadd + 320);       // 320

    const int bq = blockIdx.x;
    const int b = bq >> 11;
    const int qp = bq & 2047;
    const int tid = threadIdx.x;

    {
        int h = tid >> 4, d0 = (tid & 15) * 8;
        const float* src = q + (((size_t)(b * 16 + h)) * SS + qp) * 128 + d0;
        *(float4*)(qs + h * 128 + d0)     = *(const float4*)src;
        *(float4*)(qs + h * 128 + d0 + 4) = *(const float4*)(src + 4);
    }

    int ng, nw, wstart, tstep;
    if (qp < WIN) { ng = 0; nw = qp + 1; wstart = 0; tstep = -1; }
    else { ng = GG; nw = WIN; tstep = qp - WIN; wstart = tstep + 1; }
    const int nk = ng + nw;
    const int nchunk = (nk + 63) >> 6;

    const float scale = 0.08838834764831845f;  // 1/sqrt(128)
    const float NEG = -1e30f;

    // ---- K phase ----
    for (int c = 0; c < nchunk; ++c) {
        int cb = c << 6;
        __syncthreads();
        if (tid < 64) {
            int jk = cb + tid;
            int pos = 0; float add = NEG;
            if (jk < nk) {
                if (jk < ng) {
                    pos = gidx[b * 64 + jk];
                    add = (pos < tstep) ? 0.f : NEG;
                } else {
                    pos = wstart + (jk - ng);
                    add = mask[b * SS + pos];
                }
            }
            kpos[jk] = pos;
            kadd[jk] = add;
        }
        __syncthreads();
        {
            int row = tid >> 2, q4 = tid & 3;
            int pos = kpos[cb + row];
            const float* src = km + ((size_t)b * SS + pos) * 128;
            float* dstrow = kt + row * 129;
#pragma unroll
            for (int i = 0; i < 8; ++i) {
                int off = (q4 + (i << 2)) * 4;
                float4 v = *(const float4*)(src + off);
                dstrow[off + 0] = v.x; dstrow[off + 1] = v.y;
                dstrow[off + 2] = v.z; dstrow[off + 3] = v.w;
            }
        }
        __syncthreads();
        {
            int h0 = (tid >> 5) << 1;
            int j0 = tid & 31, j1 = j0 + 32;
            float s00 = 0, s01 = 0, s10 = 0, s11 = 0;
            const float* qa = qs + h0 * 128;
            const float* qb = qa + 128;
            const float* k0 = kt + j0 * 129;
            const float* k1 = kt + j1 * 129;
#pragma unroll 4
            for (int d = 0; d < 128; ++d) {
                float a0 = qa[d], a1 = qb[d];
                float b0 = k0[d], b1 = k1[d];
                s00 += a0 * b0; s01 += a0 * b1;
                s10 += a1 * b0; s11 += a1 * b1;
            }
            float ad0 = kadd[cb + j0], ad1 = kadd[cb + j1];
            sc[h0 * 320 + cb + j0] = s00 * scale + ad0;
            sc[h0 * 320 + cb + j1] = s01 * scale + ad1;
            sc[(h0 + 1) * 320 + cb + j0] = s10 * scale + ad0;
            sc[(h0 + 1) * 320 + cb + j1] = s11 * scale + ad1;
        }
    }
    __syncthreads();

    // ---- softmax ----
    {
        int w = tid >> 5, lane = tid & 31;
        int ntot = nchunk << 6;
        for (int hh = 0; hh < 2; ++hh) {
            float* row = sc + (w * 2 + hh) * 320;
            float m = -3.4e38f;
            for (int j = lane; j < ntot; j += 32) m = fmaxf(m, row[j]);
#pragma unroll
            for (int o = 16; o > 0; o >>= 1) m = fmaxf(m, __shfl_xor_sync(0xffffffffu, m, o));
            float sum = 0.f;
            for (int j = lane; j < ntot; j += 32) {
                float e = __expf(row[j] - m);
                row[j] = e; sum += e;
            }
#pragma unroll
            for (int o = 16; o > 0; o >>= 1) sum += __shfl_xor_sync(0xffffffffu, sum, o);
            float inv = 1.f / sum;
            for (int j = lane; j < ntot; j += 32) row[j] *= inv;
        }
    }

    // ---- V phase ----
    float acc[8] = {0, 0, 0, 0, 0, 0, 0, 0};
    const int h = tid >> 4, dl = tid & 15;
    for (int c = 0; c < nchunk; ++c) {
        int cb = c << 6;
        __syncthreads();
        {
            int row = tid >> 2, q4 = tid & 3;
            int pos = kpos[cb + row];
            const float* src = vm + ((size_t)b * SS + pos) * 128;
            float* dstrow = kt + row * 129;
#pragma unroll
            for (int i = 0; i < 8; ++i) {
                int off = (q4 + (i << 2)) * 4;
                float4 v = *(const float4*)(src + off);
                dstrow[off + 0] = v.x; dstrow[off + 1] = v.y;
                dstrow[off + 2] = v.z; dstrow[off + 3] = v.w;
            }
        }
        __syncthreads();
        const float* wrow = sc + h * 320 + cb;
#pragma unroll 2
        for (int j = 0; j < 64; ++j) {
            float wv = wrow[j];
            const float* vr = kt + j * 129 + dl;
#pragma unroll
            for (int i = 0; i < 8; ++i) acc[i] += wv * vr[i * 16];
        }
    }

    // write [B,S,H*D], tf32-rounded (feeds final GEMM directly)
    float* o = out + ((size_t)b * SS + qp) * HD + h * 128 + dl;
#pragma unroll
    for (int i = 0; i < 8; ++i) o[i * 16] = cvt_tf32(acc[i]);
}

// ---------------------------------------------------------------------------
extern "C" void kernel_launch(void* const* d_in, const int* in_sizes, int n_in,
                              void* d_out, int out_size)
{
    const float* hidden = (const float*)d_in[0];
    const float* mask   = (const float*)d_in[1];
    const int*   gidx   = (const int*)d_in[2];
    const float* Wqkv   = (const float*)d_in[3];
    const float* bqkv   = (const float*)d_in[4];
    const float* Wo     = (const float*)d_in[5];
    const float* bo     = (const float*)d_in[6];
    float* out = (float*)d_out;

    float *qkv, *qbuf, *kmp, *vmp, *attn, *hid_t, *wqkv_t, *wo_t;
    cudaGetSymbolAddress((void**)&qkv,    g_qkv);
    cudaGetSymbolAddress((void**)&qbuf,   g_q);
    cudaGetSymbolAddress((void**)&kmp,    g_km);
    cudaGetSymbolAddress((void**)&vmp,    g_vm);
    cudaGetSymbolAddress((void**)&attn,   g_attn);
    cudaGetSymbolAddress((void**)&hid_t,  g_hid_t);
    cudaGetSymbolAddress((void**)&wqkv_t, g_wqkv_t);
    cudaGetSymbolAddress((void**)&wo_t,   g_wo_t);

    const int smem_attn = ATTN_SMEM_FLOATS * 4;
    cudaFuncSetAttribute(attn_kernel, cudaFuncAttributeMaxDynamicSharedMemorySize,
                         smem_attn);
    cudaFuncSetAttribute(tf32_gemm_bias, cudaFuncAttributeMaxDynamicSharedMemorySize,
                         GEMM_SMEM_BYTES);

    // 0) tf32-preconvert GEMM operands
    {
        int n4h = (BB * SS * HD) / 4;           // 2097152
        int n4q = (HD * 3 * HD) / 4;            // 3145728
        int n4o = (HD * HD) / 4;                // 1048576
        cvt_tf32_vec<<<(n4h + 511) / 512, 512>>>((const float4*)hidden, (float4*)hid_t, n4h);
        cvt_tf32_vec<<<(n4q + 511) / 512, 512>>>((const float4*)Wqkv, (float4*)wqkv_t, n4q);
        cvt_tf32_vec<<<(n4o + 511) / 512, 512>>>((const float4*)Wo, (float4*)wo_t, n4o);
    }

    // 1) QKV GEMM: [4096,2048] @ [2048,6144] + b   (tf32 tensor cores)
    tf32_gemm_bias<<<dim3(6144 / 128, 4096 / 128), 256, GEMM_SMEM_BYTES>>>(
        hid_t, wqkv_t, bqkv, qkv, 4096, 6144, 2048);

    // 2) RoPE + split + head-mean
    rope_split_mean_kernel<<<BB * SS, 128>>>(qkv, qbuf, kmp, vmp);

    // 3) Attention (all heads per block; K/V shared across heads)
    attn_kernel<<<BB * SS, 256, smem_attn>>>(qbuf, kmp, vmp, mask, gidx, attn);

    // 4) Output GEMM: [4096,2048] @ [2048,2048] + b   (tf32 tensor cores)
    tf32_gemm_bias<<<dim3(2048 / 128, 4096 / 128), 256, GEMM_SMEM_BYTES>>>(
        attn, wo_t, bo, out, 4096, 2048, 2048);
}

// round 6
// speedup vs baseline: 2.3962x; 1.0009x over previous
#include <cuda_runtime.h>
#include <cuda_bf16.h>
#include <cstdint>
#include <math.h>

// Problem constants
#define BB 2
#define SS 2048
#define HH 16
#define DD 128
#define HD 2048
#define WIN 256
#define GG 64

// Scratch (device globals: allocation-free rule)
__device__ float g_qkv[(size_t)BB * SS * 3 * HD];   // [B,S,6144]
__device__ float g_q[(size_t)BB * HH * SS * DD];    // [B,H,S,D] roped q
__device__ float g_km[(size_t)BB * SS * DD];        // k_mean (roped)
__device__ float g_vm[(size_t)BB * SS * DD];        // v_mean
__device__ float g_attn[(size_t)BB * SS * HD];      // [B,S,H*D] attn out (tf32-rounded)
// tf32-preconverted GEMM operands
__device__ float g_hid_t[(size_t)BB * SS * HD];     // hidden, tf32
__device__ float g_wqkv_t[(size_t)HD * 3 * HD];     // W_qkv, tf32
__device__ float g_wo_t[(size_t)HD * HD];           // W_o, tf32

__device__ __forceinline__ unsigned int cvt_tf32_bits(float v) {
    unsigned int t;
    asm("cvt.rna.tf32.f32 %0, %1;" : "=r"(t) : "f"(v));
    return t;
}
__device__ __forceinline__ float cvt_tf32(float v) {
    return __uint_as_float(cvt_tf32_bits(v));
}

// ---------------------------------------------------------------------------
// Elementwise tf32 rounding (float4 vectorized). n4 = n/4.
// ---------------------------------------------------------------------------
__global__ __launch_bounds__(512)
void cvt_tf32_vec(const float4* __restrict__ in, float4* __restrict__ out, int n4)
{
    int i = blockIdx.x * blockDim.x + threadIdx.x;
    if (i < n4) {
        float4 v = in[i];
        v.x = cvt_tf32(v.x); v.y = cvt_tf32(v.y);
        v.z = cvt_tf32(v.z); v.w = cvt_tf32(v.w);
        out[i] = v;
    }
}

// ---------------------------------------------------------------------------
// TF32 tensor-core GEMM: C[M,N] = A[M,K] @ B[K,N] + bias, row-major.
// A and B must already hold tf32-rounded values. 128x128 block tile, BK=16,
// 8 warps (each 64x32 via mma.sync.m16n8k8.tf32). cp.async 16B fills plain
// layouts (A[m][k] stride 20, B[k][n] stride 132) in a 4-stage ring with ONE
// __syncthreads per K-tile; conflict-free scalar LDS gathers (bank bijection
// via odd strides). No STS, no cvt in the mainloop.
// Requires M%128==0, N%128==0, K%16==0, K/16>=3.
// ---------------------------------------------------------------------------
#define ASTRIDE 20
#define BSTRIDE 132
#define A_STG (128 * ASTRIDE)            // 2560 floats
#define B_STG (16 * BSTRIDE)             // 2112 floats
#define STG_FLOATS (A_STG + B_STG)       // 4672 floats
#define NSTAGE 4
#define GEMM_SMEM_BYTES (NSTAGE * STG_FLOATS * 4)   // 74752 B

__global__ __launch_bounds__(256, 2)
void tf32_gemm_bias(const float* __restrict__ A, const float* __restrict__ B,
                    const float* __restrict__ bias, float* __restrict__ C,
                    int M, int N, int K)
{
    extern __shared__ float smem_g[];

    const int tid  = threadIdx.x;
    const int lane = tid & 31;
    const int warp = tid >> 5;
    const int wm = warp >> 2;       // 0..1  (m half)
    const int wn = warp & 3;        // 0..3  (n quarter)
    const int brow = blockIdx.y, bcol = blockIdx.x;

    const float* Ab = A + (size_t)brow * 128 * K;
    const float* Bb = B + (size_t)bcol * 128;

    const int nk = K >> 4;

    float acc[4][4][4];
#pragma unroll
    for (int i = 0; i < 4; i++)
#pragma unroll
        for (int j = 0; j < 4; j++)
#pragma unroll
            for (int r = 0; r < 4; r++) acc[i][j][r] = 0.f;

    // ---- async-copy one K-tile into ring stage kt%NSTAGE ----
    auto issue = [&](int kt) {
        int k0 = kt << 4;
        float* st = smem_g + (kt % NSTAGE) * STG_FLOATS;
#pragma unroll
        for (int l = 0; l < 2; ++l) {
            int ca = l * 256 + tid;                 // 0..511
            int m = ca >> 2, k4 = (ca & 3) << 2;
            const float* srca = Ab + (size_t)m * K + k0 + k4;
            unsigned da = (unsigned)__cvta_generic_to_shared(st + m * ASTRIDE + k4);
            asm volatile("cp.async.cg.shared.global [%0], [%1], 16;\n"
                         :: "r"(da), "l"(srca));
            int kk = ca >> 5, n4 = (ca & 31) << 2;
            const float* srcb = Bb + (size_t)(k0 + kk) * N + n4;
            unsigned db = (unsigned)__cvta_generic_to_shared(st + A_STG + kk * BSTRIDE + n4);
            asm volatile("cp.async.cg.shared.global [%0], [%1], 16;\n"
                         :: "r"(db), "l"(srcb));
        }
    };

    const int g = lane >> 2, c = lane & 3;
    const int a_base = (wm * 64 + g) * ASTRIDE + c;
    const int b_base = c * BSTRIDE + wn * 32 + g;

    auto compute = [&](int s) {
        const float* Ast = smem_g + s * STG_FLOATS;
        const float* Bst = Ast + A_STG;
#pragma unroll
        for (int ks = 0; ks < 2; ++ks) {
            int kb = ks * 8;
            unsigned int af[4][4];
            unsigned int bf[4][2];
#pragma unroll
            for (int mil = 0; mil < 4; ++mil) {
                const float* pa = Ast + a_base + mil * (16 * ASTRIDE) + kb;
                af[mil][0] = __float_as_uint(pa[0]);
                af[mil][1] = __float_as_uint(pa[8 * ASTRIDE]);
                af[mil][2] = __float_as_uint(pa[4]);
                af[mil][3] = __float_as_uint(pa[8 * ASTRIDE + 4]);
            }
#pragma unroll
            for (int nil = 0; nil < 4; ++nil) {
                const float* pb = Bst + b_base + kb * BSTRIDE + nil * 8;
                bf[nil][0] = __float_as_uint(pb[0]);
                bf[nil][1] = __float_as_uint(pb[4 * BSTRIDE]);
            }
#pragma unroll
            for (int mil = 0; mil < 4; ++mil)
#pragma unroll
                for (int nil = 0; nil < 4; ++nil) {
                    asm volatile(
                        "mma.sync.aligned.m16n8k8.row.col.f32.tf32.tf32.f32 "
                        "{%0,%1,%2,%3}, {%4,%5,%6,%7}, {%8,%9}, {%0,%1,%2,%3};"
                        : "+f"(acc[mil][nil][0]), "+f"(acc[mil][nil][1]),
                          "+f"(acc[mil][nil][2]), "+f"(acc[mil][nil][3])
                        : "r"(af[mil][0]), "r"(af[mil][1]),
                          "r"(af[mil][2]), "r"(af[mil][3]),
                          "r"(bf[nil][0]), "r"(bf[nil][1]));
                }
        }
    };

    // ---- 4-stage pipeline, one barrier per tile ----
    issue(0);
    asm volatile("cp.async.commit_group;");
    issue(1);
    asm volatile("cp.async.commit_group;");
    issue(2);
    asm volatile("cp.async.commit_group;");

    for (int kt = 0; kt < nk; ++kt) {
        asm volatile("cp.async.wait_group 2;");     // group kt complete
        __syncthreads();                            // all threads' stage kt done
        compute(kt % NSTAGE);
        if (kt + 3 < nk) issue(kt + 3);
        asm volatile("cp.async.commit_group;");     // possibly empty
    }

    // ---- epilogue: bias + store ----
    const int tig = lane & 3;
#pragma unroll
    for (int mil = 0; mil < 4; ++mil) {
#pragma unroll
        for (int nil = 0; nil < 4; ++nil) {
            int row0 = brow * 128 + wm * 64 + mil * 16 + g;
            int col  = bcol * 128 + wn * 32 + nil * 8 + tig * 2;
            float b0 = bias[col], b1 = bias[col + 1];
            float2 v0 = make_float2(acc[mil][nil][0] + b0, acc[mil][nil][1] + b1);
            float2 v1 = make_float2(acc[mil][nil][2] + b0, acc[mil][nil][3] + b1);
            *(float2*)(C + (size_t)row0 * N + col) = v0;
            *(float2*)(C + (size_t)(row0 + 8) * N + col) = v1;
        }
    }
}

// ---------------------------------------------------------------------------
// RoPE + split + head-mean.  One block per (b,s), 128 threads (= dim d).
// ---------------------------------------------------------------------------
__global__ __launch_bounds__(128)
void rope_split_mean_kernel(const float* __restrict__ qkv,
                            float* __restrict__ qout,
                            float* __restrict__ km,
                            float* __restrict__ vm)
{
    int bs = blockIdx.x;                 // 0..4095
    int b = bs >> 11, s = bs & 2047;
    int d = threadIdx.x;                 // 0..127
    const float* base = qkv + (size_t)bs * 6144;

    float c = 1.f, sn = 0.f;
    float sgn = (d < 16) ? -1.f : 1.f;
    if (d < 32) {
        float invf = (float)exp2(-(double)(d & 15) / 16.0 * log2(10000.0));
        float ang = (float)s * invf;     // fp32 multiply matches reference
        c = (float)cos((double)ang);
        sn = (float)sin((double)ang);
    }

    float ks = 0.f, vs = 0.f;
#pragma unroll
    for (int h = 0; h < 16; ++h) {
        ks += base[h * 384 + 128 + d];
        vs += base[h * 384 + 256 + d];
    }
    ks *= 0.0625f; vs *= 0.0625f;

    float kp = __shfl_xor_sync(0xffffffffu, ks, 16);  // rope partner (d ^ 16)
    if (d < 32) ks = ks * c + sgn * kp * sn;
    km[(size_t)bs * 128 + d] = ks;
    vm[(size_t)bs * 128 + d] = vs;

#pragma unroll
    for (int h = 0; h < 16; ++h) {
        float qv = base[h * 384 + d];
        float qp = __shfl_xor_sync(0xffffffffu, qv, 16);
        float qr = (d < 32) ? (qv * c + sgn * qp * sn) : qv;
        qout[(((size_t)(b * 16 + h)) * SS + s) * 128 + d] = qr;
    }
}

// ---------------------------------------------------------------------------
// Attention. One block per (b, qpos); 256 threads; all 16 heads share K/V.
// Output written tf32-rounded (it is the A-operand of the final GEMM).
// ---------------------------------------------------------------------------
#define ATTN_SMEM_FLOATS (16*128 + 16*320 + 64*129 + 320 + 320)

__global__ __launch_bounds__(256)
void attn_kernel(const float* __restrict__ q,
                 const float* __restrict__ km,
                 const float* __restrict__ vm,
                 const float* __restrict__ mask,
                 const int* __restrict__ gidx,
                 float* __restrict__ out)
{
    extern __shared__ float sm[];
    float* qs = sm;                       // 2048
    float* sc = sm + 2048;                // 5120
    float* kt = sm + 2048 + 5120;         // 64*129 = 8256
    float* kadd = kt + 64 * 129;          // 320
    int* kpos = (int*)(kadd + 320);       // 320

    const int bq = blockIdx.x;
    const int b = bq >> 11;
    const int qp = bq & 2047;
    const int tid = threadIdx.x;

    {
        int h = tid >> 4, d0 = (tid & 15) * 8;
        const float* src = q + (((size_t)(b * 16 + h)) * SS + qp) * 128 + d0;
        *(float4*)(qs + h * 128 + d0)     = *(const float4*)src;
        *(float4*)(qs + h * 128 + d0 + 4) = *(const float4*)(src + 4);
    }

    int ng, nw, wstart, tstep;
    if (qp < WIN) { ng = 0; nw = qp + 1; wstart = 0; tstep = -1; }
    else { ng = GG; nw = WIN; tstep = qp - WIN; wstart = tstep + 1; }
    const int nk = ng + nw;
    const int nchunk = (nk + 63) >> 6;

    const float scale = 0.08838834764831845f;  // 1/sqrt(128)
    const float NEG = -1e30f;

    // ---- K phase ----
    for (int c = 0; c < nchunk; ++c) {
        int cb = c << 6;
        __syncthreads();
        if (tid < 64) {
            int jk = cb + tid;
            int pos = 0; float add = NEG;
            if (jk < nk) {
                if (jk < ng) {
                    pos = gidx[b * 64 + jk];
                    add = (pos < tstep) ? 0.f : NEG;
                } else {
                    pos = wstart + (jk - ng);
                    add = mask[b * SS + pos];
                }
            }
            kpos[jk] = pos;
            kadd[jk] = add;
        }
        __syncthreads();
        {
            int row = tid >> 2, q4 = tid & 3;
            int pos = kpos[cb + row];
            const float* src = km + ((size_t)b * SS + pos) * 128;
            float* dstrow = kt + row * 129;
#pragma unroll
            for (int i = 0; i < 8; ++i) {
                int off = (q4 + (i << 2)) * 4;
                float4 v = *(const float4*)(src + off);
                dstrow[off + 0] = v.x; dstrow[off + 1] = v.y;
                dstrow[off + 2] = v.z; dstrow[off + 3] = v.w;
            }
        }
        __syncthreads();
        {
            int h0 = (tid >> 5) << 1;
            int j0 = tid & 31, j1 = j0 + 32;
            float s00 = 0, s01 = 0, s10 = 0, s11 = 0;
            const float* qa = qs + h0 * 128;
            const float* qb = qa + 128;
            const float* k0 = kt + j0 * 129;
            const float* k1 = kt + j1 * 129;
#pragma unroll 4
            for (int d = 0; d < 128; ++d) {
                float a0 = qa[d], a1 = qb[d];
                float b0 = k0[d], b1 = k1[d];
                s00 += a0 * b0; s01 += a0 * b1;
                s10 += a1 * b0; s11 += a1 * b1;
            }
            float ad0 = kadd[cb + j0], ad1 = kadd[cb + j1];
            sc[h0 * 320 + cb + j0] = s00 * scale + ad0;
            sc[h0 * 320 + cb + j1] = s01 * scale + ad1;
            sc[(h0 + 1) * 320 + cb + j0] = s10 * scale + ad0;
            sc[(h0 + 1) * 320 + cb + j1] = s11 * scale + ad1;
        }
    }
    __syncthreads();

    // ---- softmax ----
    {
        int w = tid >> 5, lane = tid & 31;
        int ntot = nchunk << 6;
        for (int hh = 0; hh < 2; ++hh) {
            float* row = sc + (w * 2 + hh) * 320;
            float m = -3.4e38f;
            for (int j = lane; j < ntot; j += 32) m = fmaxf(m, row[j]);
#pragma unroll
            for (int o = 16; o > 0; o >>= 1) m = fmaxf(m, __shfl_xor_sync(0xffffffffu, m, o));
            float sum = 0.f;
            for (int j = lane; j < ntot; j += 32) {
                float e = __expf(row[j] - m);
                row[j] = e; sum += e;
            }
#pragma unroll
            for (int o = 16; o > 0; o >>= 1) sum += __shfl_xor_sync(0xffffffffu, sum, o);
            float inv = 1.f / sum;
            for (int j = lane; j < ntot; j += 32) row[j] *= inv;
        }
    }

    // ---- V phase ----
    float acc[8] = {0, 0, 0, 0, 0, 0, 0, 0};
    const int h = tid >> 4, dl = tid & 15;
    for (int c = 0; c < nchunk; ++c) {
        int cb = c << 6;
        __syncthreads();
        {
            int row = tid >> 2, q4 = tid & 3;
            int pos = kpos[cb + row];
            const float* src = vm + ((size_t)b * SS + pos) * 128;
            float* dstrow = kt + row * 129;
#pragma unroll
            for (int i = 0; i < 8; ++i) {
                int off = (q4 + (i << 2)) * 4;
                float4 v = *(const float4*)(src + off);
                dstrow[off + 0] = v.x; dstrow[off + 1] = v.y;
                dstrow[off + 2] = v.z; dstrow[off + 3] = v.w;
            }
        }
        __syncthreads();
        const float* wrow = sc + h * 320 + cb;
#pragma unroll 2
        for (int j = 0; j < 64; ++j) {
            float wv = wrow[j];
            const float* vr = kt + j * 129 + dl;
#pragma unroll
            for (int i = 0; i < 8; ++i) acc[i] += wv * vr[i * 16];
        }
    }

    // write [B,S,H*D], tf32-rounded (feeds final GEMM directly)
    float* o = out + ((size_t)b * SS + qp) * HD + h * 128 + dl;
#pragma unroll
    for (int i = 0; i < 8; ++i) o[i * 16] = cvt_tf32(acc[i]);
}

// ---------------------------------------------------------------------------
extern "C" void kernel_launch(void* const* d_in, const int* in_sizes, int n_in,
                              void* d_out, int out_size)
{
    const float* hidden = (const float*)d_in[0];
    const float* mask   = (const float*)d_in[1];
    const int*   gidx   = (const int*)d_in[2];
    const float* Wqkv   = (const float*)d_in[3];
    const float* bqkv   = (const float*)d_in[4];
    const float* Wo     = (const float*)d_in[5];
    const float* bo     = (const float*)d_in[6];
    float* out = (float*)d_out;

    float *qkv, *qbuf, *kmp, *vmp, *attn, *hid_t, *wqkv_t, *wo_t;
    cudaGetSymbolAddress((void**)&qkv,    g_qkv);
    cudaGetSymbolAddress((void**)&qbuf,   g_q);
    cudaGetSymbolAddress((void**)&kmp,    g_km);
    cudaGetSymbolAddress((void**)&vmp,    g_vm);
    cudaGetSymbolAddress((void**)&attn,   g_attn);
    cudaGetSymbolAddress((void**)&hid_t,  g_hid_t);
    cudaGetSymbolAddress((void**)&wqkv_t, g_wqkv_t);
    cudaGetSymbolAddress((void**)&wo_t,   g_wo_t);

    const int smem_attn = ATTN_SMEM_FLOATS * 4;
    cudaFuncSetAttribute(attn_kernel, cudaFuncAttributeMaxDynamicSharedMemorySize,
                         smem_attn);
    cudaFuncSetAttribute(tf32_gemm_bias, cudaFuncAttributeMaxDynamicSharedMemorySize,
                         GEMM_SMEM_BYTES);

    // 0) tf32-preconvert GEMM operands
    {
        int n4h = (BB * SS * HD) / 4;           // 2097152
        int n4q = (HD * 3 * HD) / 4;            // 3145728
        int n4o = (HD * HD) / 4;                // 1048576
        cvt_tf32_vec<<<(n4h + 511) / 512, 512>>>((const float4*)hidden, (float4*)hid_t, n4h);
        cvt_tf32_vec<<<(n4q + 511) / 512, 512>>>((const float4*)Wqkv, (float4*)wqkv_t, n4q);
        cvt_tf32_vec<<<(n4o + 511) / 512, 512>>>((const float4*)Wo, (float4*)wo_t, n4o);
    }

    // 1) QKV GEMM: [4096,2048] @ [2048,6144] + b   (tf32 tensor cores)
    tf32_gemm_bias<<<dim3(6144 / 128, 4096 / 128), 256, GEMM_SMEM_BYTES>>>(
        hid_t, wqkv_t, bqkv, qkv, 4096, 6144, 2048);

    // 2) RoPE + split + head-mean
    rope_split_mean_kernel<<<BB * SS, 128>>>(qkv, qbuf, kmp, vmp);

    // 3) Attention (all heads per block; K/V shared across heads)
    attn_kernel<<<BB * SS, 256, smem_attn>>>(qbuf, kmp, vmp, mask, gidx, attn);

    // 4) Output GEMM: [4096,2048] @ [2048,2048] + b   (tf32 tensor cores)
    tf32_gemm_bias<<<dim3(2048 / 128, 4096 / 128), 256, GEMM_SMEM_BYTES>>>(
        attn, wo_t, bo, out, 4096, 2048, 2048);
}

// round 7
// speedup vs baseline: 3.1923x; 1.3322x over previous
#include <cuda_runtime.h>
#include <cuda_bf16.h>
#include <cstdint>
#include <math.h>

#define BB 2
#define SS 2048
#define HH 16
#define DD 128
#define HD 2048
#define WIN 256
#define GG 64

__device__ float g_qkv[(size_t)BB * SS * 3 * HD];
__device__ float g_q[(size_t)BB * HH * SS * DD];
__device__ float g_km[(size_t)BB * SS * DD];
__device__ float g_vm[(size_t)BB * SS * DD];
__device__ float g_attn[(size_t)BB * SS * HD];
__device__ float g_hid_t[(size_t)BB * SS * HD];
__device__ float g_wqkv_t[(size_t)HD * 3 * HD];
__device__ float g_wo_t[(size_t)HD * HD];

__device__ __forceinline__ unsigned int cvt_tf32_bits(float v) {
    unsigned int t;
    asm("cvt.rna.tf32.f32 %0, %1;" : "=r"(t) : "f"(v));
    return t;
}
__device__ __forceinline__ float cvt_tf32(float v) {
    return __uint_as_float(cvt_tf32_bits(v));
}
__device__ __forceinline__ void mma_tf32(float* acc, const unsigned* a, const unsigned* b) {
    asm volatile(
        "mma.sync.aligned.m16n8k8.row.col.f32.tf32.tf32.f32 "
        "{%0,%1,%2,%3}, {%4,%5,%6,%7}, {%8,%9}, {%0,%1,%2,%3};"
        : "+f"(acc[0]), "+f"(acc[1]), "+f"(acc[2]), "+f"(acc[3])
        : "r"(a[0]), "r"(a[1]), "r"(a[2]), "r"(a[3]), "r"(b[0]), "r"(b[1]));
}

__global__ __launch_bounds__(512)
void cvt_tf32_vec(const float4* __restrict__ in, float4* __restrict__ out, int n4)
{
    int i = blockIdx.x * blockDim.x + threadIdx.x;
    if (i < n4) {
        float4 v = in[i];
        v.x = cvt_tf32(v.x); v.y = cvt_tf32(v.y);
        v.z = cvt_tf32(v.z); v.w = cvt_tf32(v.w);
        out[i] = v;
    }
}

// ---------------- TF32 GEMM (unchanged, proven) ----------------
#define ASTRIDE 20
#define BSTRIDE 132
#define A_STG (128 * ASTRIDE)
#define B_STG (16 * BSTRIDE)
#define STG_FLOATS (A_STG + B_STG)
#define NSTAGE 4
#define GEMM_SMEM_BYTES (NSTAGE * STG_FLOATS * 4)

__global__ __launch_bounds__(256, 2)
void tf32_gemm_bias(const float* __restrict__ A, const float* __restrict__ B,
                    const float* __restrict__ bias, float* __restrict__ C,
                    int M, int N, int K)
{
    extern __shared__ float smem_g[];
    const int tid = threadIdx.x, lane = tid & 31, warp = tid >> 5;
    const int wm = warp >> 2, wn = warp & 3;
    const int brow = blockIdx.y, bcol = blockIdx.x;
    const float* Ab = A + (size_t)brow * 128 * K;
    const float* Bb = B + (size_t)bcol * 128;
    const int nk = K >> 4;

    float acc[4][4][4];
#pragma unroll
    for (int i = 0; i < 4; i++)
#pragma unroll
        for (int j = 0; j < 4; j++)
#pragma unroll
            for (int r = 0; r < 4; r++) acc[i][j][r] = 0.f;

    auto issue = [&](int kt) {
        int k0 = kt << 4;
        float* st = smem_g + (kt % NSTAGE) * STG_FLOATS;
#pragma unroll
        for (int l = 0; l < 2; ++l) {
            int ca = l * 256 + tid;
            int m = ca >> 2, k4 = (ca & 3) << 2;
            unsigned da = (unsigned)__cvta_generic_to_shared(st + m * ASTRIDE + k4);
            asm volatile("cp.async.cg.shared.global [%0], [%1], 16;\n"
                         :: "r"(da), "l"(Ab + (size_t)m * K + k0 + k4));
            int kk = ca >> 5, n4 = (ca & 31) << 2;
            unsigned db = (unsigned)__cvta_generic_to_shared(st + A_STG + kk * BSTRIDE + n4);
            asm volatile("cp.async.cg.shared.global [%0], [%1], 16;\n"
                         :: "r"(db), "l"(Bb + (size_t)(k0 + kk) * N + n4));
        }
    };

    const int g = lane >> 2, c = lane & 3;
    const int a_base = (wm * 64 + g) * ASTRIDE + c;
    const int b_base = c * BSTRIDE + wn * 32 + g;

    auto compute = [&](int s) {
        const float* Ast = smem_g + s * STG_FLOATS;
        const float* Bst = Ast + A_STG;
#pragma unroll
        for (int ks = 0; ks < 2; ++ks) {
            int kb = ks * 8;
            unsigned af[4][4], bf[4][2];
#pragma unroll
            for (int mil = 0; mil < 4; ++mil) {
                const float* pa = Ast + a_base + mil * (16 * ASTRIDE) + kb;
                af[mil][0] = __float_as_uint(pa[0]);
                af[mil][1] = __float_as_uint(pa[8 * ASTRIDE]);
                af[mil][2] = __float_as_uint(pa[4]);
                af[mil][3] = __float_as_uint(pa[8 * ASTRIDE + 4]);
            }
#pragma unroll
            for (int nil = 0; nil < 4; ++nil) {
                const float* pb = Bst + b_base + kb * BSTRIDE + nil * 8;
                bf[nil][0] = __float_as_uint(pb[0]);
                bf[nil][1] = __float_as_uint(pb[4 * BSTRIDE]);
            }
#pragma unroll
            for (int mil = 0; mil < 4; ++mil)
#pragma unroll
                for (int nil = 0; nil < 4; ++nil)
                    mma_tf32(acc[mil][nil], af[mil], bf[nil]);
        }
    };

    issue(0); asm volatile("cp.async.commit_group;");
    issue(1); asm volatile("cp.async.commit_group;");
    issue(2); asm volatile("cp.async.commit_group;");
    for (int kt = 0; kt < nk; ++kt) {
        asm volatile("cp.async.wait_group 2;");
        __syncthreads();
        compute(kt % NSTAGE);
        if (kt + 3 < nk) issue(kt + 3);
        asm volatile("cp.async.commit_group;");
    }

    const int tig = lane & 3;
#pragma unroll
    for (int mil = 0; mil < 4; ++mil)
#pragma unroll
        for (int nil = 0; nil < 4; ++nil) {
            int row0 = brow * 128 + wm * 64 + mil * 16 + g;
            int col  = bcol * 128 + wn * 32 + nil * 8 + tig * 2;
            float b0 = bias[col], b1 = bias[col + 1];
            *(float2*)(C + (size_t)row0 * N + col) =
                make_float2(acc[mil][nil][0] + b0, acc[mil][nil][1] + b1);
            *(float2*)(C + (size_t)(row0 + 8) * N + col) =
                make_float2(acc[mil][nil][2] + b0, acc[mil][nil][3] + b1);
        }
}

// ---------------- RoPE + split + head-mean (unchanged) ----------------
__global__ __launch_bounds__(128)
void rope_split_mean_kernel(const float* __restrict__ qkv, float* __restrict__ qout,
                            float* __restrict__ km, float* __restrict__ vm)
{
    int bs = blockIdx.x;
    int b = bs >> 11, s = bs & 2047;
    int d = threadIdx.x;
    const float* base = qkv + (size_t)bs * 6144;

    float c = 1.f, sn = 0.f;
    float sgn = (d < 16) ? -1.f : 1.f;
    if (d < 32) {
        float invf = (float)exp2(-(double)(d & 15) / 16.0 * log2(10000.0));
        float ang = (float)s * invf;
        c = (float)cos((double)ang);
        sn = (float)sin((double)ang);
    }
    float ks = 0.f, vs = 0.f;
#pragma unroll
    for (int h = 0; h < 16; ++h) {
        ks += base[h * 384 + 128 + d];
        vs += base[h * 384 + 256 + d];
    }
    ks *= 0.0625f; vs *= 0.0625f;
    float kp = __shfl_xor_sync(0xffffffffu, ks, 16);
    if (d < 32) ks = ks * c + sgn * kp * sn;
    km[(size_t)bs * 128 + d] = ks;
    vm[(size_t)bs * 128 + d] = vs;
#pragma unroll
    for (int h = 0; h < 16; ++h) {
        float qv = base[h * 384 + d];
        float qp = __shfl_xor_sync(0xffffffffu, qv, 16);
        float qr = (d < 32) ? (qv * c + sgn * qp * sn) : qv;
        qout[(((size_t)(b * 16 + h)) * SS + s) * 128 + d] = qr;
    }
}

// ---------------- MMA attention ----------------
// Block = (b, 16-q tile, 8 heads); warp w = head hg*8+w, one m16 tile.
// Chunks of 64 keys; flash online softmax; QK plain tf32; PV 3-term split.
#define OFF_K    0                   // K chunk [64][132]
#define OFF_VH   8448                // V_hi [64][136]
#define OFF_VL   17152               // V_lo [64][136]
#define OFF_P    25856               // per warp: hi[16][68], lo[16][68]
#define OFF_KPOS 43264               // int[384]
#define OFF_KADD 43648               // float[384]
#define ATTN2_FLOATS 44032
#define ATTN2_BYTES (ATTN2_FLOATS * 4)

__global__ __launch_bounds__(256, 1)
void attn_mma(const float* __restrict__ q, const float* __restrict__ km,
              const float* __restrict__ vm, const float* __restrict__ mask,
              const int* __restrict__ gidx, float* __restrict__ out)
{
    extern __shared__ float sm[];
    int* kpos = (int*)(sm + OFF_KPOS);
    float* kadd = sm + OFF_KADD;

    const int qp0 = blockIdx.x * 16, hg = blockIdx.y, b = blockIdx.z;
    const int tid = threadIdx.x, warp = tid >> 5, lane = tid & 31;
    const int g = lane >> 2, c2 = lane & 3, tig = c2;
    const bool caseA = (qp0 >= WIN);
    const int NCH = caseA ? 6 : ((qp0 + 79) >> 6);
    const float scale = 0.08838834764831845f;

    // slot tables
    for (int j = tid; j < 384; j += 256) {
        int pos = 1 << 27; float ka = 0.f;
        if (caseA) {
            if (j < 64) pos = gidx[b * GG + j];
            else { int p = qp0 - 255 + (j - 64);
                   if (p < SS) { pos = p; ka = mask[b * SS + p]; } }
        } else if (j < qp0 + 16) { pos = j; ka = mask[b * SS + j]; }
        kpos[j] = pos; kadd[j] = ka;
    }

    // Q fragments (pre-scaled) into registers
    const int h = hg * 8 + warp;
    unsigned qf[16][4];
    {
        const float* qb = q + (((size_t)(b * 16 + h)) * SS + qp0) * 128;
#pragma unroll
        for (int ks = 0; ks < 16; ++ks) {
            int d0 = ks * 8 + c2;
            qf[ks][0] = cvt_tf32_bits(qb[g * 128 + d0] * scale);
            qf[ks][1] = cvt_tf32_bits(qb[(g + 8) * 128 + d0] * scale);
            qf[ks][2] = cvt_tf32_bits(qb[g * 128 + d0 + 4] * scale);
            qf[ks][3] = cvt_tf32_bits(qb[(g + 8) * 128 + d0 + 4] * scale);
        }
    }
    __syncthreads();

    float m0 = -1e30f, m1 = -1e30f, l0 = 0.f, l1 = 0.f;
    float oacc[16][4];
#pragma unroll
    for (int dt = 0; dt < 16; ++dt)
#pragma unroll
        for (int e = 0; e < 4; ++e) oacc[dt][e] = 0.f;

    float* Pw = sm + OFF_P + warp * 2176;     // hi [16][68]; lo at +1088

    for (int ch = 0; ch < NCH; ++ch) {
        const int cb = ch << 6;
        const bool isglob = caseA && (ch == 0);

        // load K (tf32) + V (hi/lo) chunk
        {
            int r = tid >> 2, c0 = (tid & 3) * 32;
            int pos = kpos[cb + r]; if (pos >= SS) pos = 0;
            const float* kvp = km + ((size_t)b * SS + pos) * 128 + c0;
            const float* vvp = vm + ((size_t)b * SS + pos) * 128 + c0;
            float* kd = sm + OFF_K + r * 132 + c0;
            float* vh = sm + OFF_VH + r * 136 + c0;
            float* vl = sm + OFF_VL + r * 136 + c0;
#pragma unroll
            for (int j = 0; j < 8; ++j) {
                float4 a = *(const float4*)(kvp + j * 4);
                a.x = cvt_tf32(a.x); a.y = cvt_tf32(a.y);
                a.z = cvt_tf32(a.z); a.w = cvt_tf32(a.w);
                *(float4*)(kd + j * 4) = a;
                float4 v = *(const float4*)(vvp + j * 4);
                float4 hi = make_float4(cvt_tf32(v.x), cvt_tf32(v.y),
                                        cvt_tf32(v.z), cvt_tf32(v.w));
                *(float4*)(vh + j * 4) = hi;
                *(float4*)(vl + j * 4) = make_float4(
                    cvt_tf32(v.x - hi.x), cvt_tf32(v.y - hi.y),
                    cvt_tf32(v.z - hi.z), cvt_tf32(v.w - hi.w));
            }
        }
        __syncthreads();

        // QK^T
        float S[8][4];
#pragma unroll
        for (int nt = 0; nt < 8; ++nt)
#pragma unroll
            for (int e = 0; e < 4; ++e) S[nt][e] = 0.f;
#pragma unroll
        for (int ks = 0; ks < 16; ++ks) {
#pragma unroll
            for (int nt = 0; nt < 8; ++nt) {
                const float* pk = sm + OFF_K + (nt * 8 + g) * 132 + ks * 8 + c2;
                unsigned bf[2] = {__float_as_uint(pk[0]), __float_as_uint(pk[4])};
                mma_tf32(S[nt], qf[ks], bf);
            }
        }

        // mask + online softmax
        float mc0 = -2e30f, mc1 = -2e30f;
#pragma unroll
        for (int nt = 0; nt < 8; ++nt) {
            int s0 = cb + nt * 8 + 2 * tig;
#pragma unroll
            for (int e = 0; e < 2; ++e) {
                int p = kpos[s0 + e]; float ka = kadd[s0 + e];
                int r0 = qp0 + g, r1 = r0 + 8;
                bool v0, v1;
                if (isglob) { v0 = p < r0 - 256; v1 = p < r1 - 256; }
                else { v0 = (p <= r0) && (p + 255 >= r0);
                       v1 = (p <= r1) && (p + 255 >= r1); }
                S[nt][e]     = v0 ? S[nt][e] + ka     : -2e30f;
                S[nt][e + 2] = v1 ? S[nt][e + 2] + ka : -2e30f;
                mc0 = fmaxf(mc0, S[nt][e]);
                mc1 = fmaxf(mc1, S[nt][e + 2]);
            }
        }
        mc0 = fmaxf(mc0, __shfl_xor_sync(~0u, mc0, 1));
        mc0 = fmaxf(mc0, __shfl_xor_sync(~0u, mc0, 2));
        mc1 = fmaxf(mc1, __shfl_xor_sync(~0u, mc1, 1));
        mc1 = fmaxf(mc1, __shfl_xor_sync(~0u, mc1, 2));
        float mn0 = fmaxf(m0, mc0), mn1 = fmaxf(m1, mc1);
        float cr0 = __expf(m0 - mn0), cr1 = __expf(m1 - mn1);
        m0 = mn0; m1 = mn1;
        float lc0 = 0.f, lc1 = 0.f;
#pragma unroll
        for (int nt = 0; nt < 8; ++nt) {
            S[nt][0] = __expf(S[nt][0] - mn0); S[nt][1] = __expf(S[nt][1] - mn0);
            S[nt][2] = __expf(S[nt][2] - mn1); S[nt][3] = __expf(S[nt][3] - mn1);
            lc0 += S[nt][0] + S[nt][1]; lc1 += S[nt][2] + S[nt][3];
        }
        lc0 += __shfl_xor_sync(~0u, lc0, 1); lc0 += __shfl_xor_sync(~0u, lc0, 2);
        lc1 += __shfl_xor_sync(~0u, lc1, 1); lc1 += __shfl_xor_sync(~0u, lc1, 2);
        l0 = l0 * cr0 + lc0; l1 = l1 * cr1 + lc1;
#pragma unroll
        for (int dt = 0; dt < 16; ++dt) {
            oacc[dt][0] *= cr0; oacc[dt][1] *= cr0;
            oacc[dt][2] *= cr1; oacc[dt][3] *= cr1;
        }
        // store P hi/lo (A-frag readable, stride 68)
#pragma unroll
        for (int nt = 0; nt < 8; ++nt) {
            int col = nt * 8 + 2 * tig;
            float h00 = cvt_tf32(S[nt][0]), h01 = cvt_tf32(S[nt][1]);
            float h10 = cvt_tf32(S[nt][2]), h11 = cvt_tf32(S[nt][3]);
            *(float2*)(Pw + g * 68 + col)            = make_float2(h00, h01);
            *(float2*)(Pw + (g + 8) * 68 + col)      = make_float2(h10, h11);
            *(float2*)(Pw + 1088 + g * 68 + col)     =
                make_float2(cvt_tf32(S[nt][0] - h00), cvt_tf32(S[nt][1] - h01));
            *(float2*)(Pw + 1088 + (g + 8) * 68 + col) =
                make_float2(cvt_tf32(S[nt][2] - h10), cvt_tf32(S[nt][3] - h11));
        }
        __syncwarp();

        // PV (3-term split)
#pragma unroll
        for (int pk = 0; pk < 8; ++pk) {
            const float* ph = Pw + pk * 8 + c2;
            unsigned ah[4] = {__float_as_uint(ph[g * 68]),
                              __float_as_uint(ph[(g + 8) * 68]),
                              __float_as_uint(ph[g * 68 + 4]),
                              __float_as_uint(ph[(g + 8) * 68 + 4])};
            const float* pl = ph + 1088;
            unsigned al[4] = {__float_as_uint(pl[g * 68]),
                              __float_as_uint(pl[(g + 8) * 68]),
                              __float_as_uint(pl[g * 68 + 4]),
                              __float_as_uint(pl[(g + 8) * 68 + 4])};
#pragma unroll
            for (int dt = 0; dt < 16; ++dt) {
                const float* vh = sm + OFF_VH + (pk * 8 + c2) * 136 + dt * 8 + g;
                const float* vl = sm + OFF_VL + (pk * 8 + c2) * 136 + dt * 8 + g;
                unsigned bh[2] = {__float_as_uint(vh[0]), __float_as_uint(vh[4 * 136])};
                unsigned bl[2] = {__float_as_uint(vl[0]), __float_as_uint(vl[4 * 136])};
                mma_tf32(oacc[dt], ah, bh);
                mma_tf32(oacc[dt], al, bh);
                mma_tf32(oacc[dt], ah, bl);
            }
        }
        __syncthreads();
    }

    // epilogue: /l, tf32-round (feeds GEMM2), store
    float inv0 = 1.f / l0, inv1 = 1.f / l1;
    float* o0 = out + ((size_t)b * SS + qp0 + g) * HD + h * 128 + 2 * tig;
    float* o1 = out + ((size_t)b * SS + qp0 + g + 8) * HD + h * 128 + 2 * tig;
#pragma unroll
    for (int dt = 0; dt < 16; ++dt) {
        *(float2*)(o0 + dt * 8) = make_float2(cvt_tf32(oacc[dt][0] * inv0),
                                              cvt_tf32(oacc[dt][1] * inv0));
        *(float2*)(o1 + dt * 8) = make_float2(cvt_tf32(oacc[dt][2] * inv1),
                                              cvt_tf32(oacc[dt][3] * inv1));
    }
}

// ---------------------------------------------------------------------------
extern "C" void kernel_launch(void* const* d_in, const int* in_sizes, int n_in,
                              void* d_out, int out_size)
{
    const float* hidden = (const float*)d_in[0];
    const float* mask   = (const float*)d_in[1];
    const int*   gidx   = (const int*)d_in[2];
    const float* Wqkv   = (const float*)d_in[3];
    const float* bqkv   = (const float*)d_in[4];
    const float* Wo     = (const float*)d_in[5];
    const float* bo     = (const float*)d_in[6];
    float* out = (float*)d_out;

    float *qkv, *qbuf, *kmp, *vmp, *attn, *hid_t, *wqkv_t, *wo_t;
    cudaGetSymbolAddress((void**)&qkv,    g_qkv);
    cudaGetSymbolAddress((void**)&qbuf,   g_q);
    cudaGetSymbolAddress((void**)&kmp,    g_km);
    cudaGetSymbolAddress((void**)&vmp,    g_vm);
    cudaGetSymbolAddress((void**)&attn,   g_attn);
    cudaGetSymbolAddress((void**)&hid_t,  g_hid_t);
    cudaGetSymbolAddress((void**)&wqkv_t, g_wqkv_t);
    cudaGetSymbolAddress((void**)&wo_t,   g_wo_t);

    cudaFuncSetAttribute(attn_mma, cudaFuncAttributeMaxDynamicSharedMemorySize,
                         ATTN2_BYTES);
    cudaFuncSetAttribute(tf32_gemm_bias, cudaFuncAttributeMaxDynamicSharedMemorySize,
                         GEMM_SMEM_BYTES);

    int n4h = (BB * SS * HD) / 4, n4q = (HD * 3 * HD) / 4, n4o = (HD * HD) / 4;
    cvt_tf32_vec<<<(n4h + 511) / 512, 512>>>((const float4*)hidden, (float4*)hid_t, n4h);
    cvt_tf32_vec<<<(n4q + 511) / 512, 512>>>((const float4*)Wqkv, (float4*)wqkv_t, n4q);
    cvt_tf32_vec<<<(n4o + 511) / 512, 512>>>((const float4*)Wo, (float4*)wo_t, n4o);

    tf32_gemm_bias<<<dim3(6144 / 128, 4096 / 128), 256, GEMM_SMEM_BYTES>>>(
        hid_t, wqkv_t, bqkv, qkv, 4096, 6144, 2048);

    rope_split_mean_kernel<<<BB * SS, 128>>>(qkv, qbuf, kmp, vmp);

    attn_mma<<<dim3(SS / 16, 2, BB), 256, ATTN2_BYTES>>>(
        qbuf, kmp, vmp, mask, gidx, attn);

    tf32_gemm_bias<<<dim3(2048 / 128, 4096 / 128), 256, GEMM_SMEM_BYTES>>>(
        attn, wo_t, bo, out, 4096, 2048, 2048);
}

// round 8
// speedup vs baseline: 4.8446x; 1.5176x over previous
#include <cuda_runtime.h>
#include <cuda_bf16.h>
#include <cstdint>
#include <math.h>

#define BB 2
#define SS 2048
#define HH 16
#define DD 128
#define HD 2048
#define WIN 256
#define GG 64
#define NPACK 2304   // 2048 q cols + 128 k_mean + 128 v_mean

__device__ float g_wpack[(size_t)HD * NPACK];   // packed+averaged W, tf32
__device__ float g_bpack[NPACK];
__device__ float g_qraw[(size_t)BB * SS * NPACK]; // GEMM1 out: q | k_mean | v_mean
__device__ float g_q[(size_t)BB * HH * SS * DD];
__device__ float g_km[(size_t)BB * SS * DD];
__device__ float g_vm[(size_t)BB * SS * DD];
__device__ float g_attn[(size_t)BB * SS * HD];
__device__ float g_hid_t[(size_t)BB * SS * HD];
__device__ float g_wo_t[(size_t)HD * HD];

__device__ __forceinline__ unsigned int cvt_tf32_bits(float v) {
    unsigned int t;
    asm("cvt.rna.tf32.f32 %0, %1;" : "=r"(t) : "f"(v));
    return t;
}
__device__ __forceinline__ float cvt_tf32(float v) {
    return __uint_as_float(cvt_tf32_bits(v));
}
__device__ __forceinline__ void mma_tf32(float* acc, const unsigned* a, const unsigned* b) {
    asm volatile(
        "mma.sync.aligned.m16n8k8.row.col.f32.tf32.tf32.f32 "
        "{%0,%1,%2,%3}, {%4,%5,%6,%7}, {%8,%9}, {%0,%1,%2,%3};"
        : "+f"(acc[0]), "+f"(acc[1]), "+f"(acc[2]), "+f"(acc[3])
        : "r"(a[0]), "r"(a[1]), "r"(a[2]), "r"(a[3]), "r"(b[0]), "r"(b[1]));
}

__global__ __launch_bounds__(512)
void cvt_tf32_vec(const float4* __restrict__ in, float4* __restrict__ out, int n4)
{
    int i = blockIdx.x * blockDim.x + threadIdx.x;
    if (i < n4) {
        float4 v = in[i];
        v.x = cvt_tf32(v.x); v.y = cvt_tf32(v.y);
        v.z = cvt_tf32(v.z); v.w = cvt_tf32(v.w);
        out[i] = v;
    }
}

// Pack W_qkv [2048][6144] -> Wp [2048][2304] (tf32):
//   n <  2048 : q column  h=n>>7, d=n&127  -> col h*384 + d
//   n >= 2048 : head-mean of col h*384 + 128 + (n-2048)   (k then v, contiguous)
__global__ __launch_bounds__(256)
void pack_w(const float* __restrict__ W, float* __restrict__ Wp)
{
    long idx = (long)blockIdx.x * 256 + threadIdx.x;
    if (idx >= (long)HD * NPACK) return;
    int c = (int)(idx / NPACK), n = (int)(idx % NPACK);
    const float* row = W + (size_t)c * 6144;
    float v;
    if (n < 2048) {
        v = row[(n >> 7) * 384 + (n & 127)];
    } else {
        int off = 128 + (n - 2048);
        float s = 0.f;
#pragma unroll
        for (int h = 0; h < 16; ++h) s += row[h * 384 + off];
        v = s * 0.0625f;
    }
    Wp[idx] = cvt_tf32(v);
}

__global__ __launch_bounds__(256)
void pack_b(const float* __restrict__ bq, float* __restrict__ bp)
{
    int n = blockIdx.x * 256 + threadIdx.x;
    if (n >= NPACK) return;
    float v;
    if (n < 2048) {
        v = bq[(n >> 7) * 384 + (n & 127)];
    } else {
        int off = 128 + (n - 2048);
        float s = 0.f;
#pragma unroll
        for (int h = 0; h < 16; ++h) s += bq[h * 384 + off];
        v = s * 0.0625f;
    }
    bp[n] = v;
}

// ---------------- TF32 GEMM (unchanged, proven) ----------------
#define ASTRIDE 20
#define BSTRIDE 132
#define A_STG (128 * ASTRIDE)
#define B_STG (16 * BSTRIDE)
#define STG_FLOATS (A_STG + B_STG)
#define NSTAGE 4
#define GEMM_SMEM_BYTES (NSTAGE * STG_FLOATS * 4)

__global__ __launch_bounds__(256, 2)
void tf32_gemm_bias(const float* __restrict__ A, const float* __restrict__ B,
                    const float* __restrict__ bias, float* __restrict__ C,
                    int M, int N, int K)
{
    extern __shared__ float smem_g[];
    const int tid = threadIdx.x, lane = tid & 31, warp = tid >> 5;
    const int wm = warp >> 2, wn = warp & 3;
    const int brow = blockIdx.y, bcol = blockIdx.x;
    const float* Ab = A + (size_t)brow * 128 * K;
    const float* Bb = B + (size_t)bcol * 128;
    const int nk = K >> 4;

    float acc[4][4][4];
#pragma unroll
    for (int i = 0; i < 4; i++)
#pragma unroll
        for (int j = 0; j < 4; j++)
#pragma unroll
            for (int r = 0; r < 4; r++) acc[i][j][r] = 0.f;

    auto issue = [&](int kt) {
        int k0 = kt << 4;
        float* st = smem_g + (kt % NSTAGE) * STG_FLOATS;
#pragma unroll
        for (int l = 0; l < 2; ++l) {
            int ca = l * 256 + tid;
            int m = ca >> 2, k4 = (ca & 3) << 2;
            unsigned da = (unsigned)__cvta_generic_to_shared(st + m * ASTRIDE + k4);
            asm volatile("cp.async.cg.shared.global [%0], [%1], 16;\n"
                         :: "r"(da), "l"(Ab + (size_t)m * K + k0 + k4));
            int kk = ca >> 5, n4 = (ca & 31) << 2;
            unsigned db = (unsigned)__cvta_generic_to_shared(st + A_STG + kk * BSTRIDE + n4);
            asm volatile("cp.async.cg.shared.global [%0], [%1], 16;\n"
                         :: "r"(db), "l"(Bb + (size_t)(k0 + kk) * N + n4));
        }
    };

    const int g = lane >> 2, c = lane & 3;
    const int a_base = (wm * 64 + g) * ASTRIDE + c;
    const int b_base = c * BSTRIDE + wn * 32 + g;

    auto compute = [&](int s) {
        const float* Ast = smem_g + s * STG_FLOATS;
        const float* Bst = Ast + A_STG;
#pragma unroll
        for (int ks = 0; ks < 2; ++ks) {
            int kb = ks * 8;
            unsigned af[4][4], bf[4][2];
#pragma unroll
            for (int mil = 0; mil < 4; ++mil) {
                const float* pa = Ast + a_base + mil * (16 * ASTRIDE) + kb;
                af[mil][0] = __float_as_uint(pa[0]);
                af[mil][1] = __float_as_uint(pa[8 * ASTRIDE]);
                af[mil][2] = __float_as_uint(pa[4]);
                af[mil][3] = __float_as_uint(pa[8 * ASTRIDE + 4]);
            }
#pragma unroll
            for (int nil = 0; nil < 4; ++nil) {
                const float* pb = Bst + b_base + kb * BSTRIDE + nil * 8;
                bf[nil][0] = __float_as_uint(pb[0]);
                bf[nil][1] = __float_as_uint(pb[4 * BSTRIDE]);
            }
#pragma unroll
            for (int mil = 0; mil < 4; ++mil)
#pragma unroll
                for (int nil = 0; nil < 4; ++nil)
                    mma_tf32(acc[mil][nil], af[mil], bf[nil]);
        }
    };

    issue(0); asm volatile("cp.async.commit_group;");
    issue(1); asm volatile("cp.async.commit_group;");
    issue(2); asm volatile("cp.async.commit_group;");
    for (int kt = 0; kt < nk; ++kt) {
        asm volatile("cp.async.wait_group 2;");
        __syncthreads();
        compute(kt % NSTAGE);
        if (kt + 3 < nk) issue(kt + 3);
        asm volatile("cp.async.commit_group;");
    }

    const int tig = lane & 3;
#pragma unroll
    for (int mil = 0; mil < 4; ++mil)
#pragma unroll
        for (int nil = 0; nil < 4; ++nil) {
            int row0 = brow * 128 + wm * 64 + mil * 16 + g;
            int col  = bcol * 128 + wn * 32 + nil * 8 + tig * 2;
            float b0 = bias[col], b1 = bias[col + 1];
            *(float2*)(C + (size_t)row0 * N + col) =
                make_float2(acc[mil][nil][0] + b0, acc[mil][nil][1] + b1);
            *(float2*)(C + (size_t)(row0 + 8) * N + col) =
                make_float2(acc[mil][nil][2] + b0, acc[mil][nil][3] + b1);
        }
}

// ---------------- RoPE + split (reads packed GEMM1 output) ----------------
__global__ __launch_bounds__(128)
void rope_split_kernel(const float* __restrict__ qraw, float* __restrict__ qout,
                       float* __restrict__ km, float* __restrict__ vm)
{
    int bs = blockIdx.x;
    int b = bs >> 11, s = bs & 2047;
    int d = threadIdx.x;
    const float* base = qraw + (size_t)bs * NPACK;

    float c = 1.f, sn = 0.f;
    float sgn = (d < 16) ? -1.f : 1.f;
    if (d < 32) {
        float invf = (float)exp2(-(double)(d & 15) / 16.0 * log2(10000.0));
        float ang = (float)s * invf;
        c = (float)cos((double)ang);
        sn = (float)sin((double)ang);
    }

    float kv = base[2048 + d];
    float vv = base[2176 + d];
    float kp = __shfl_xor_sync(0xffffffffu, kv, 16);
    if (d < 32) kv = kv * c + sgn * kp * sn;
    km[(size_t)bs * 128 + d] = kv;
    vm[(size_t)bs * 128 + d] = vv;

#pragma unroll
    for (int h = 0; h < 16; ++h) {
        float qv = base[h * 128 + d];
        float qp = __shfl_xor_sync(0xffffffffu, qv, 16);
        float qr = (d < 32) ? (qv * c + sgn * qp * sn) : qv;
        qout[(((size_t)(b * 16 + h)) * SS + s) * 128 + d] = qr;
    }
}

// ---------------- MMA attention (unchanged, proven) ----------------
#define OFF_K    0
#define OFF_VH   8448
#define OFF_VL   17152
#define OFF_P    25856
#define OFF_KPOS 43264
#define OFF_KADD 43648
#define ATTN2_FLOATS 44032
#define ATTN2_BYTES (ATTN2_FLOATS * 4)

__global__ __launch_bounds__(256, 1)
void attn_mma(const float* __restrict__ q, const float* __restrict__ km,
              const float* __restrict__ vm, const float* __restrict__ mask,
              const int* __restrict__ gidx, float* __restrict__ out)
{
    extern __shared__ float sm[];
    int* kpos = (int*)(sm + OFF_KPOS);
    float* kadd = sm + OFF_KADD;

    const int qp0 = blockIdx.x * 16, hg = blockIdx.y, b = blockIdx.z;
    const int tid = threadIdx.x, warp = tid >> 5, lane = tid & 31;
    const int g = lane >> 2, c2 = lane & 3, tig = c2;
    const bool caseA = (qp0 >= WIN);
    const int NCH = caseA ? 6 : ((qp0 + 79) >> 6);
    const float scale = 0.08838834764831845f;

    for (int j = tid; j < 384; j += 256) {
        int pos = 1 << 27; float ka = 0.f;
        if (caseA) {
            if (j < 64) pos = gidx[b * GG + j];
            else { int p = qp0 - 255 + (j - 64);
                   if (p < SS) { pos = p; ka = mask[b * SS + p]; } }
        } else if (j < qp0 + 16) { pos = j; ka = mask[b * SS + j]; }
        kpos[j] = pos; kadd[j] = ka;
    }

    const int h = hg * 8 + warp;
    unsigned qf[16][4];
    {
        const float* qb = q + (((size_t)(b * 16 + h)) * SS + qp0) * 128;
#pragma unroll
        for (int ks = 0; ks < 16; ++ks) {
            int d0 = ks * 8 + c2;
            qf[ks][0] = cvt_tf32_bits(qb[g * 128 + d0] * scale);
            qf[ks][1] = cvt_tf32_bits(qb[(g + 8) * 128 + d0] * scale);
            qf[ks][2] = cvt_tf32_bits(qb[g * 128 + d0 + 4] * scale);
            qf[ks][3] = cvt_tf32_bits(qb[(g + 8) * 128 + d0 + 4] * scale);
        }
    }
    __syncthreads();

    float m0 = -1e30f, m1 = -1e30f, l0 = 0.f, l1 = 0.f;
    float oacc[16][4];
#pragma unroll
    for (int dt = 0; dt < 16; ++dt)
#pragma unroll
        for (int e = 0; e < 4; ++e) oacc[dt][e] = 0.f;

    float* Pw = sm + OFF_P + warp * 2176;

    for (int ch = 0; ch < NCH; ++ch) {
        const int cb = ch << 6;
        const bool isglob = caseA && (ch == 0);

        {
            int r = tid >> 2, c0 = (tid & 3) * 32;
            int pos = kpos[cb + r]; if (pos >= SS) pos = 0;
            const float* kvp = km + ((size_t)b * SS + pos) * 128 + c0;
            const float* vvp = vm + ((size_t)b * SS + pos) * 128 + c0;
            float* kd = sm + OFF_K + r * 132 + c0;
            float* vh = sm + OFF_VH + r * 136 + c0;
            float* vl = sm + OFF_VL + r * 136 + c0;
#pragma unroll
            for (int j = 0; j < 8; ++j) {
                float4 a = *(const float4*)(kvp + j * 4);
                a.x = cvt_tf32(a.x); a.y = cvt_tf32(a.y);
                a.z = cvt_tf32(a.z); a.w = cvt_tf32(a.w);
                *(float4*)(kd + j * 4) = a;
                float4 v = *(const float4*)(vvp + j * 4);
                float4 hi = make_float4(cvt_tf32(v.x), cvt_tf32(v.y),
                                        cvt_tf32(v.z), cvt_tf32(v.w));
                *(float4*)(vh + j * 4) = hi;
                *(float4*)(vl + j * 4) = make_float4(
                    cvt_tf32(v.x - hi.x), cvt_tf32(v.y - hi.y),
                    cvt_tf32(v.z - hi.z), cvt_tf32(v.w - hi.w));
            }
        }
        __syncthreads();

        float S[8][4];
#pragma unroll
        for (int nt = 0; nt < 8; ++nt)
#pragma unroll
            for (int e = 0; e < 4; ++e) S[nt][e] = 0.f;
#pragma unroll
        for (int ks = 0; ks < 16; ++ks) {
#pragma unroll
            for (int nt = 0; nt < 8; ++nt) {
                const float* pk = sm + OFF_K + (nt * 8 + g) * 132 + ks * 8 + c2;
                unsigned bf[2] = {__float_as_uint(pk[0]), __float_as_uint(pk[4])};
                mma_tf32(S[nt], qf[ks], bf);
            }
        }

        float mc0 = -2e30f, mc1 = -2e30f;
#pragma unroll
        for (int nt = 0; nt < 8; ++nt) {
            int s0 = cb + nt * 8 + 2 * tig;
#pragma unroll
            for (int e = 0; e < 2; ++e) {
                int p = kpos[s0 + e]; float ka = kadd[s0 + e];
                int r0 = qp0 + g, r1 = r0 + 8;
                bool v0, v1;
                if (isglob) { v0 = p < r0 - 256; v1 = p < r1 - 256; }
                else { v0 = (p <= r0) && (p + 255 >= r0);
                       v1 = (p <= r1) && (p + 255 >= r1); }
                S[nt][e]     = v0 ? S[nt][e] + ka     : -2e30f;
                S[nt][e + 2] = v1 ? S[nt][e + 2] + ka : -2e30f;
                mc0 = fmaxf(mc0, S[nt][e]);
                mc1 = fmaxf(mc1, S[nt][e + 2]);
            }
        }
        mc0 = fmaxf(mc0, __shfl_xor_sync(~0u, mc0, 1));
        mc0 = fmaxf(mc0, __shfl_xor_sync(~0u, mc0, 2));
        mc1 = fmaxf(mc1, __shfl_xor_sync(~0u, mc1, 1));
        mc1 = fmaxf(mc1, __shfl_xor_sync(~0u, mc1, 2));
        float mn0 = fmaxf(m0, mc0), mn1 = fmaxf(m1, mc1);
        float cr0 = __expf(m0 - mn0), cr1 = __expf(m1 - mn1);
        m0 = mn0; m1 = mn1;
        float lc0 = 0.f, lc1 = 0.f;
#pragma unroll
        for (int nt = 0; nt < 8; ++nt) {
            S[nt][0] = __expf(S[nt][0] - mn0); S[nt][1] = __expf(S[nt][1] - mn0);
            S[nt][2] = __expf(S[nt][2] - mn1); S[nt][3] = __expf(S[nt][3] - mn1);
            lc0 += S[nt][0] + S[nt][1]; lc1 += S[nt][2] + S[nt][3];
        }
        lc0 += __shfl_xor_sync(~0u, lc0, 1); lc0 += __shfl_xor_sync(~0u, lc0, 2);
        lc1 += __shfl_xor_sync(~0u, lc1, 1); lc1 += __shfl_xor_sync(~0u, lc1, 2);
        l0 = l0 * cr0 + lc0; l1 = l1 * cr1 + lc1;
#pragma unroll
        for (int dt = 0; dt < 16; ++dt) {
            oacc[dt][0] *= cr0; oacc[dt][1] *= cr0;
            oacc[dt][2] *= cr1; oacc[dt][3] *= cr1;
        }
#pragma unroll
        for (int nt = 0; nt < 8; ++nt) {
            int col = nt * 8 + 2 * tig;
            float h00 = cvt_tf32(S[nt][0]), h01 = cvt_tf32(S[nt][1]);
            float h10 = cvt_tf32(S[nt][2]), h11 = cvt_tf32(S[nt][3]);
            *(float2*)(Pw + g * 68 + col)            = make_float2(h00, h01);
            *(float2*)(Pw + (g + 8) * 68 + col)      = make_float2(h10, h11);
            *(float2*)(Pw + 1088 + g * 68 + col)     =
                make_float2(cvt_tf32(S[nt][0] - h00), cvt_tf32(S[nt][1] - h01));
            *(float2*)(Pw + 1088 + (g + 8) * 68 + col) =
                make_float2(cvt_tf32(S[nt][2] - h10), cvt_tf32(S[nt][3] - h11));
        }
        __syncwarp();

#pragma unroll
        for (int pk = 0; pk < 8; ++pk) {
            const float* ph = Pw + pk * 8 + c2;
            unsigned ah[4] = {__float_as_uint(ph[g * 68]),
                              __float_as_uint(ph[(g + 8) * 68]),
                              __float_as_uint(ph[g * 68 + 4]),
                              __float_as_uint(ph[(g + 8) * 68 + 4])};
            const float* pl = ph + 1088;
            unsigned al[4] = {__float_as_uint(pl[g * 68]),
                              __float_as_uint(pl[(g + 8) * 68]),
                              __float_as_uint(pl[g * 68 + 4]),
                              __float_as_uint(pl[(g + 8) * 68 + 4])};
#pragma unroll
            for (int dt = 0; dt < 16; ++dt) {
                const float* vh = sm + OFF_VH + (pk * 8 + c2) * 136 + dt * 8 + g;
                const float* vl = sm + OFF_VL + (pk * 8 + c2) * 136 + dt * 8 + g;
                unsigned bh[2] = {__float_as_uint(vh[0]), __float_as_uint(vh[4 * 136])};
                unsigned bl[2] = {__float_as_uint(vl[0]), __float_as_uint(vl[4 * 136])};
                mma_tf32(oacc[dt], ah, bh);
                mma_tf32(oacc[dt], al, bh);
                mma_tf32(oacc[dt], ah, bl);
            }
        }
        __syncthreads();
    }

    float inv0 = 1.f / l0, inv1 = 1.f / l1;
    float* o0 = out + ((size_t)b * SS + qp0 + g) * HD + h * 128 + 2 * tig;
    float* o1 = out + ((size_t)b * SS + qp0 + g + 8) * HD + h * 128 + 2 * tig;
#pragma unroll
    for (int dt = 0; dt < 16; ++dt) {
        *(float2*)(o0 + dt * 8) = make_float2(cvt_tf32(oacc[dt][0] * inv0),
                                              cvt_tf32(oacc[dt][1] * inv0));
        *(float2*)(o1 + dt * 8) = make_float2(cvt_tf32(oacc[dt][2] * inv1),
                                              cvt_tf32(oacc[dt][3] * inv1));
    }
}

// ---------------------------------------------------------------------------
extern "C" void kernel_launch(void* const* d_in, const int* in_sizes, int n_in,
                              void* d_out, int out_size)
{
    const float* hidden = (const float*)d_in[0];
    const float* mask   = (const float*)d_in[1];
    const int*   gidx   = (const int*)d_in[2];
    const float* Wqkv   = (const float*)d_in[3];
    const float* bqkv   = (const float*)d_in[4];
    const float* Wo     = (const float*)d_in[5];
    const float* bo     = (const float*)d_in[6];
    float* out = (float*)d_out;

    float *wpack, *bpack, *qraw, *qbuf, *kmp, *vmp, *attn, *hid_t, *wo_t;
    cudaGetSymbolAddress((void**)&wpack, g_wpack);
    cudaGetSymbolAddress((void**)&bpack, g_bpack);
    cudaGetSymbolAddress((void**)&qraw,  g_qraw);
    cudaGetSymbolAddress((void**)&qbuf,  g_q);
    cudaGetSymbolAddress((void**)&kmp,   g_km);
    cudaGetSymbolAddress((void**)&vmp,   g_vm);
    cudaGetSymbolAddress((void**)&attn,  g_attn);
    cudaGetSymbolAddress((void**)&hid_t, g_hid_t);
    cudaGetSymbolAddress((void**)&wo_t,  g_wo_t);

    cudaFuncSetAttribute(attn_mma, cudaFuncAttributeMaxDynamicSharedMemorySize,
                         ATTN2_BYTES);
    cudaFuncSetAttribute(tf32_gemm_bias, cudaFuncAttributeMaxDynamicSharedMemorySize,
                         GEMM_SMEM_BYTES);

    // 0) operand prep
    {
        long nw = (long)HD * NPACK;
        pack_w<<<(unsigned)((nw + 255) / 256), 256>>>(Wqkv, wpack);
        pack_b<<<(NPACK + 255) / 256, 256>>>(bqkv, bpack);
        int n4h = (BB * SS * HD) / 4, n4o = (HD * HD) / 4;
        cvt_tf32_vec<<<(n4h + 511) / 512, 512>>>((const float4*)hidden,
                                                 (float4*)hid_t, n4h);
        cvt_tf32_vec<<<(n4o + 511) / 512, 512>>>((const float4*)Wo,
                                                 (float4*)wo_t, n4o);
    }

    // 1) fused Q + head-mean-KV GEMM: [4096,2048] @ [2048,2304] + b
    tf32_gemm_bias<<<dim3(NPACK / 128, 4096 / 128), 256, GEMM_SMEM_BYTES>>>(
        hid_t, wpack, bpack, qraw, 4096, NPACK, 2048);

    // 2) RoPE + split
    rope_split_kernel<<<BB * SS, 128>>>(qraw, qbuf, kmp, vmp);

    // 3) MMA attention
    attn_mma<<<dim3(SS / 16, 2, BB), 256, ATTN2_BYTES>>>(
        qbuf, kmp, vmp, mask, gidx, attn);

    // 4) Output GEMM: [4096,2048] @ [2048,2048] + b
    tf32_gemm_bias<<<dim3(2048 / 128, 4096 / 128), 256, GEMM_SMEM_BYTES>>>(
        attn, wo_t, bo, out, 4096, 2048, 2048);
}

// round 9
// speedup vs baseline: 5.3871x; 1.1120x over previous
#include <cuda_runtime.h>
#include <cuda_bf16.h>
#include <cstdint>
#include <math.h>

#define BB 2
#define SS 2048
#define HH 16
#define DD 128
#define HD 2048
#define WIN 256
#define GG 64
#define NPACK 2304   // 2048 q cols + 128 k_mean + 128 v_mean

__device__ float g_wpack[(size_t)HD * NPACK];
__device__ float g_bpack[NPACK];
__device__ float g_qraw[(size_t)BB * SS * NPACK];
__device__ float g_q[(size_t)BB * HH * SS * DD];
__device__ float g_km[(size_t)BB * SS * DD];
__device__ float g_vm[(size_t)BB * SS * DD];
__device__ float g_attn[(size_t)BB * SS * HD];
__device__ float g_hid_t[(size_t)BB * SS * HD];
__device__ float g_wo_t[(size_t)HD * HD];

__device__ __forceinline__ unsigned int cvt_tf32_bits(float v) {
    unsigned int t;
    asm("cvt.rna.tf32.f32 %0, %1;" : "=r"(t) : "f"(v));
    return t;
}
__device__ __forceinline__ float cvt_tf32(float v) {
    return __uint_as_float(cvt_tf32_bits(v));
}
__device__ __forceinline__ void mma_tf32(float* acc, const unsigned* a, const unsigned* b) {
    asm volatile(
        "mma.sync.aligned.m16n8k8.row.col.f32.tf32.tf32.f32 "
        "{%0,%1,%2,%3}, {%4,%5,%6,%7}, {%8,%9}, {%0,%1,%2,%3};"
        : "+f"(acc[0]), "+f"(acc[1]), "+f"(acc[2]), "+f"(acc[3])
        : "r"(a[0]), "r"(a[1]), "r"(a[2]), "r"(a[3]), "r"(b[0]), "r"(b[1]));
}

__global__ __launch_bounds__(512)
void cvt_tf32_vec(const float4* __restrict__ in, float4* __restrict__ out, int n4)
{
    int i = blockIdx.x * blockDim.x + threadIdx.x;
    if (i < n4) {
        float4 v = in[i];
        v.x = cvt_tf32(v.x); v.y = cvt_tf32(v.y);
        v.z = cvt_tf32(v.z); v.w = cvt_tf32(v.w);
        out[i] = v;
    }
}

__global__ __launch_bounds__(256)
void pack_w(const float* __restrict__ W, float* __restrict__ Wp)
{
    long idx = (long)blockIdx.x * 256 + threadIdx.x;
    if (idx >= (long)HD * NPACK) return;
    int c = (int)(idx / NPACK), n = (int)(idx % NPACK);
    const float* row = W + (size_t)c * 6144;
    float v;
    if (n < 2048) {
        v = row[(n >> 7) * 384 + (n & 127)];
    } else {
        int off = 128 + (n - 2048);
        float s = 0.f;
#pragma unroll
        for (int h = 0; h < 16; ++h) s += row[h * 384 + off];
        v = s * 0.0625f;
    }
    Wp[idx] = cvt_tf32(v);
}

__global__ __launch_bounds__(256)
void pack_b(const float* __restrict__ bq, float* __restrict__ bp)
{
    int n = blockIdx.x * 256 + threadIdx.x;
    if (n >= NPACK) return;
    float v;
    if (n < 2048) {
        v = bq[(n >> 7) * 384 + (n & 127)];
    } else {
        int off = 128 + (n - 2048);
        float s = 0.f;
#pragma unroll
        for (int h = 0; h < 16; ++h) s += bq[h * 384 + off];
        v = s * 0.0625f;
    }
    bp[n] = v;
}

// ---------------- TF32 GEMM: BK=32, 3-stage ring ----------------
#define ASTRIDE 36
#define BSTRIDE 132
#define A_STG (128 * ASTRIDE)            // 4608 floats
#define B_STG (32 * BSTRIDE)             // 4224 floats
#define STG_FLOATS (A_STG + B_STG)       // 8832 floats
#define NSTAGE 3
#define GEMM_SMEM_BYTES (NSTAGE * STG_FLOATS * 4)   // 105984 B

__global__ __launch_bounds__(256, 2)
void tf32_gemm_bias(const float* __restrict__ A, const float* __restrict__ B,
                    const float* __restrict__ bias, float* __restrict__ C,
                    int M, int N, int K)
{
    extern __shared__ float smem_g[];
    const int tid = threadIdx.x, lane = tid & 31, warp = tid >> 5;
    const int wm = warp >> 2, wn = warp & 3;
    const int brow = blockIdx.y, bcol = blockIdx.x;
    const float* Ab = A + (size_t)brow * 128 * K;
    const float* Bb = B + (size_t)bcol * 128;
    const int nk = K >> 5;     // 32-wide K tiles

    float acc[4][4][4];
#pragma unroll
    for (int i = 0; i < 4; i++)
#pragma unroll
        for (int j = 0; j < 4; j++)
#pragma unroll
            for (int r = 0; r < 4; r++) acc[i][j][r] = 0.f;

    auto issue = [&](int kt) {
        int k0 = kt << 5;
        float* st = smem_g + (kt % NSTAGE) * STG_FLOATS;
#pragma unroll
        for (int l = 0; l < 4; ++l) {
            int ca = l * 256 + tid;                 // 0..1023
            int m = ca >> 3, k4 = (ca & 7) << 2;    // A: 128x32
            unsigned da = (unsigned)__cvta_generic_to_shared(st + m * ASTRIDE + k4);
            asm volatile("cp.async.cg.shared.global [%0], [%1], 16;\n"
                         :: "r"(da), "l"(Ab + (size_t)m * K + k0 + k4));
            int kk = ca >> 5, n4 = (ca & 31) << 2;  // B: 32x128
            unsigned db = (unsigned)__cvta_generic_to_shared(st + A_STG + kk * BSTRIDE + n4);
            asm volatile("cp.async.cg.shared.global [%0], [%1], 16;\n"
                         :: "r"(db), "l"(Bb + (size_t)(k0 + kk) * N + n4));
        }
    };

    const int g = lane >> 2, c = lane & 3;
    const int a_base = (wm * 64 + g) * ASTRIDE + c;
    const int b_base = c * BSTRIDE + wn * 32 + g;

    auto compute = [&](int s) {
        const float* Ast = smem_g + s * STG_FLOATS;
        const float* Bst = Ast + A_STG;
#pragma unroll
        for (int ks = 0; ks < 4; ++ks) {
            int kb = ks * 8;
            unsigned af[4][4], bf[4][2];
#pragma unroll
            for (int mil = 0; mil < 4; ++mil) {
                const float* pa = Ast + a_base + mil * (16 * ASTRIDE) + kb;
                af[mil][0] = __float_as_uint(pa[0]);
                af[mil][1] = __float_as_uint(pa[8 * ASTRIDE]);
                af[mil][2] = __float_as_uint(pa[4]);
                af[mil][3] = __float_as_uint(pa[8 * ASTRIDE + 4]);
            }
#pragma unroll
            for (int nil = 0; nil < 4; ++nil) {
                const float* pb = Bst + b_base + kb * BSTRIDE + nil * 8;
                bf[nil][0] = __float_as_uint(pb[0]);
                bf[nil][1] = __float_as_uint(pb[4 * BSTRIDE]);
            }
#pragma unroll
            for (int mil = 0; mil < 4; ++mil)
#pragma unroll
                for (int nil = 0; nil < 4; ++nil)
                    mma_tf32(acc[mil][nil], af[mil], bf[nil]);
        }
    };

    issue(0); asm volatile("cp.async.commit_group;");
    issue(1); asm volatile("cp.async.commit_group;");
    for (int kt = 0; kt < nk; ++kt) {
        asm volatile("cp.async.wait_group 1;");
        __syncthreads();
        compute(kt % NSTAGE);
        if (kt + 2 < nk) issue(kt + 2);
        asm volatile("cp.async.commit_group;");
    }

    const int tig = lane & 3;
#pragma unroll
    for (int mil = 0; mil < 4; ++mil)
#pragma unroll
        for (int nil = 0; nil < 4; ++nil) {
            int row0 = brow * 128 + wm * 64 + mil * 16 + g;
            int col  = bcol * 128 + wn * 32 + nil * 8 + tig * 2;
            float b0 = bias[col], b1 = bias[col + 1];
            *(float2*)(C + (size_t)row0 * N + col) =
                make_float2(acc[mil][nil][0] + b0, acc[mil][nil][1] + b1);
            *(float2*)(C + (size_t)(row0 + 8) * N + col) =
                make_float2(acc[mil][nil][2] + b0, acc[mil][nil][3] + b1);
        }
}

// ---------------- RoPE + split ----------------
__global__ __launch_bounds__(128)
void rope_split_kernel(const float* __restrict__ qraw, float* __restrict__ qout,
                       float* __restrict__ km, float* __restrict__ vm)
{
    int bs = blockIdx.x;
    int b = bs >> 11, s = bs & 2047;
    int d = threadIdx.x;
    const float* base = qraw + (size_t)bs * NPACK;

    float c = 1.f, sn = 0.f;
    float sgn = (d < 16) ? -1.f : 1.f;
    if (d < 32) {
        float invf = (float)exp2(-(double)(d & 15) / 16.0 * log2(10000.0));
        float ang = (float)s * invf;
        c = (float)cos((double)ang);
        sn = (float)sin((double)ang);
    }

    float kv = base[2048 + d];
    float vv = base[2176 + d];
    float kp = __shfl_xor_sync(0xffffffffu, kv, 16);
    if (d < 32) kv = kv * c + sgn * kp * sn;
    km[(size_t)bs * 128 + d] = kv;
    vm[(size_t)bs * 128 + d] = vv;

#pragma unroll
    for (int h = 0; h < 16; ++h) {
        float qv = base[h * 128 + d];
        float qp = __shfl_xor_sync(0xffffffffu, qv, 16);
        float qr = (d < 32) ? (qv * c + sgn * qp * sn) : qv;
        qout[(((size_t)(b * 16 + h)) * SS + s) * 128 + d] = qr;
    }
}

// ---------------- MMA attention (2-term PV: exact-P x tf32(V)) ----------------
#define OFF_K    0                    // K chunk [64][132]
#define OFF_VH   8448                 // V tf32 [64][136]
#define OFF_P    17152                // per warp: hi[16][68], lo[16][68]
#define OFF_KPOS 34560                // int[384]
#define OFF_KADD 34944                // float[384]
#define ATTN2_FLOATS 35328
#define ATTN2_BYTES (ATTN2_FLOATS * 4)

__global__ __launch_bounds__(256, 1)
void attn_mma(const float* __restrict__ q, const float* __restrict__ km,
              const float* __restrict__ vm, const float* __restrict__ mask,
              const int* __restrict__ gidx, float* __restrict__ out)
{
    extern __shared__ float sm[];
    int* kpos = (int*)(sm + OFF_KPOS);
    float* kadd = sm + OFF_KADD;

    const int qp0 = blockIdx.x * 16, hg = blockIdx.y, b = blockIdx.z;
    const int tid = threadIdx.x, warp = tid >> 5, lane = tid & 31;
    const int g = lane >> 2, c2 = lane & 3, tig = c2;
    const bool caseA = (qp0 >= WIN);
    const int NCH = caseA ? 6 : ((qp0 + 79) >> 6);
    const float scale = 0.08838834764831845f;

    for (int j = tid; j < 384; j += 256) {
        int pos = 1 << 27; float ka = 0.f;
        if (caseA) {
            if (j < 64) pos = gidx[b * GG + j];
            else { int p = qp0 - 255 + (j - 64);
                   if (p < SS) { pos = p; ka = mask[b * SS + p]; } }
        } else if (j < qp0 + 16) { pos = j; ka = mask[b * SS + j]; }
        kpos[j] = pos; kadd[j] = ka;
    }

    const int h = hg * 8 + warp;
    unsigned qf[16][4];
    {
        const float* qb = q + (((size_t)(b * 16 + h)) * SS + qp0) * 128;
#pragma unroll
        for (int ks = 0; ks < 16; ++ks) {
            int d0 = ks * 8 + c2;
            qf[ks][0] = cvt_tf32_bits(qb[g * 128 + d0] * scale);
            qf[ks][1] = cvt_tf32_bits(qb[(g + 8) * 128 + d0] * scale);
            qf[ks][2] = cvt_tf32_bits(qb[g * 128 + d0 + 4] * scale);
            qf[ks][3] = cvt_tf32_bits(qb[(g + 8) * 128 + d0 + 4] * scale);
        }
    }
    __syncthreads();

    float m0 = -1e30f, m1 = -1e30f, l0 = 0.f, l1 = 0.f;
    float oacc[16][4];
#pragma unroll
    for (int dt = 0; dt < 16; ++dt)
#pragma unroll
        for (int e = 0; e < 4; ++e) oacc[dt][e] = 0.f;

    float* Pw = sm + OFF_P + warp * 2176;

    for (int ch = 0; ch < NCH; ++ch) {
        const int cb = ch << 6;
        const bool isglob = caseA && (ch == 0);

        {
            int r = tid >> 2, c0 = (tid & 3) * 32;
            int pos = kpos[cb + r]; if (pos >= SS) pos = 0;
            const float* kvp = km + ((size_t)b * SS + pos) * 128 + c0;
            const float* vvp = vm + ((size_t)b * SS + pos) * 128 + c0;
            float* kd = sm + OFF_K + r * 132 + c0;
            float* vh = sm + OFF_VH + r * 136 + c0;
#pragma unroll
            for (int j = 0; j < 8; ++j) {
                float4 a = *(const float4*)(kvp + j * 4);
                a.x = cvt_tf32(a.x); a.y = cvt_tf32(a.y);
                a.z = cvt_tf32(a.z); a.w = cvt_tf32(a.w);
                *(float4*)(kd + j * 4) = a;
                float4 v = *(const float4*)(vvp + j * 4);
                v.x = cvt_tf32(v.x); v.y = cvt_tf32(v.y);
                v.z = cvt_tf32(v.z); v.w = cvt_tf32(v.w);
                *(float4*)(vh + j * 4) = v;
            }
        }
        __syncthreads();

        float S[8][4];
#pragma unroll
        for (int nt = 0; nt < 8; ++nt)
#pragma unroll
            for (int e = 0; e < 4; ++e) S[nt][e] = 0.f;
#pragma unroll
        for (int ks = 0; ks < 16; ++ks) {
#pragma unroll
            for (int nt = 0; nt < 8; ++nt) {
                const float* pk = sm + OFF_K + (nt * 8 + g) * 132 + ks * 8 + c2;
                unsigned bf[2] = {__float_as_uint(pk[0]), __float_as_uint(pk[4])};
                mma_tf32(S[nt], qf[ks], bf);
            }
        }

        float mc0 = -2e30f, mc1 = -2e30f;
#pragma unroll
        for (int nt = 0; nt < 8; ++nt) {
            int s0 = cb + nt * 8 + 2 * tig;
#pragma unroll
            for (int e = 0; e < 2; ++e) {
                int p = kpos[s0 + e]; float ka = kadd[s0 + e];
                int r0 = qp0 + g, r1 = r0 + 8;
                bool v0, v1;
                if (isglob) { v0 = p < r0 - 256; v1 = p < r1 - 256; }
                else { v0 = (p <= r0) && (p + 255 >= r0);
                       v1 = (p <= r1) && (p + 255 >= r1); }
                S[nt][e]     = v0 ? S[nt][e] + ka     : -2e30f;
                S[nt][e + 2] = v1 ? S[nt][e + 2] + ka : -2e30f;
                mc0 = fmaxf(mc0, S[nt][e]);
                mc1 = fmaxf(mc1, S[nt][e + 2]);
            }
        }
        mc0 = fmaxf(mc0, __shfl_xor_sync(~0u, mc0, 1));
        mc0 = fmaxf(mc0, __shfl_xor_sync(~0u, mc0, 2));
        mc1 = fmaxf(mc1, __shfl_xor_sync(~0u, mc1, 1));
        mc1 = fmaxf(mc1, __shfl_xor_sync(~0u, mc1, 2));
        float mn0 = fmaxf(m0, mc0), mn1 = fmaxf(m1, mc1);
        float cr0 = __expf(m0 - mn0), cr1 = __expf(m1 - mn1);
        m0 = mn0; m1 = mn1;
        float lc0 = 0.f, lc1 = 0.f;
#pragma unroll
        for (int nt = 0; nt < 8; ++nt) {
            S[nt][0] = __expf(S[nt][0] - mn0); S[nt][1] = __expf(S[nt][1] - mn0);
            S[nt][2] = __expf(S[nt][2] - mn1); S[nt][3] = __expf(S[nt][3] - mn1);
            lc0 += S[nt][0] + S[nt][1]; lc1 += S[nt][2] + S[nt][3];
        }
        lc0 += __shfl_xor_sync(~0u, lc0, 1); lc0 += __shfl_xor_sync(~0u, lc0, 2);
        lc1 += __shfl_xor_sync(~0u, lc1, 1); lc1 += __shfl_xor_sync(~0u, lc1, 2);
        l0 = l0 * cr0 + lc0; l1 = l1 * cr1 + lc1;
#pragma unroll
        for (int dt = 0; dt < 16; ++dt) {
            oacc[dt][0] *= cr0; oacc[dt][1] *= cr0;
            oacc[dt][2] *= cr1; oacc[dt][3] *= cr1;
        }
#pragma unroll
        for (int nt = 0; nt < 8; ++nt) {
            int col = nt * 8 + 2 * tig;
            float h00 = cvt_tf32(S[nt][0]), h01 = cvt_tf32(S[nt][1]);
            float h10 = cvt_tf32(S[nt][2]), h11 = cvt_tf32(S[nt][3]);
            *(float2*)(Pw + g * 68 + col)            = make_float2(h00, h01);
            *(float2*)(Pw + (g + 8) * 68 + col)      = make_float2(h10, h11);
            *(float2*)(Pw + 1088 + g * 68 + col)     =
                make_float2(cvt_tf32(S[nt][0] - h00), cvt_tf32(S[nt][1] - h01));
            *(float2*)(Pw + 1088 + (g + 8) * 68 + col) =
                make_float2(cvt_tf32(S[nt][2] - h10), cvt_tf32(S[nt][3] - h11));
        }
        __syncwarp();

#pragma unroll
        for (int pk = 0; pk < 8; ++pk) {
            const float* ph = Pw + pk * 8 + c2;
            unsigned ah[4] = {__float_as_uint(ph[g * 68]),
                              __float_as_uint(ph[(g + 8) * 68]),
                              __float_as_uint(ph[g * 68 + 4]),
                              __float_as_uint(ph[(g + 8) * 68 + 4])};
            const float* pl = ph + 1088;
            unsigned al[4] = {__float_as_uint(pl[g * 68]),
                              __float_as_uint(pl[(g + 8) * 68]),
                              __float_as_uint(pl[g * 68 + 4]),
                              __float_as_uint(pl[(g + 8) * 68 + 4])};
#pragma unroll
            for (int dt = 0; dt < 16; ++dt) {
                const float* vh = sm + OFF_VH + (pk * 8 + c2) * 136 + dt * 8 + g;
                unsigned bh[2] = {__float_as_uint(vh[0]), __float_as_uint(vh[4 * 136])};
                mma_tf32(oacc[dt], ah, bh);
                mma_tf32(oacc[dt], al, bh);
            }
        }
        __syncthreads();
    }

    float inv0 = 1.f / l0, inv1 = 1.f / l1;
    float* o0 = out + ((size_t)b * SS + qp0 + g) * HD + h * 128 + 2 * tig;
    float* o1 = out + ((size_t)b * SS + qp0 + g + 8) * HD + h * 128 + 2 * tig;
#pragma unroll
    for (int dt = 0; dt < 16; ++dt) {
        *(float2*)(o0 + dt * 8) = make_float2(cvt_tf32(oacc[dt][0] * inv0),
                                              cvt_tf32(oacc[dt][1] * inv0));
        *(float2*)(o1 + dt * 8) = make_float2(cvt_tf32(oacc[dt][2] * inv1),
                                              cvt_tf32(oacc[dt][3] * inv1));
    }
}

// ---------------------------------------------------------------------------
extern "C" void kernel_launch(void* const* d_in, const int* in_sizes, int n_in,
                              void* d_out, int out_size)
{
    const float* hidden = (const float*)d_in[0];
    const float* mask   = (const float*)d_in[1];
    const int*   gidx   = (const int*)d_in[2];
    const float* Wqkv   = (const float*)d_in[3];
    const float* bqkv   = (const float*)d_in[4];
    const float* Wo     = (const float*)d_in[5];
    const float* bo     = (const float*)d_in[6];
    float* out = (float*)d_out;

    float *wpack, *bpack, *qraw, *qbuf, *kmp, *vmp, *attn, *hid_t, *wo_t;
    cudaGetSymbolAddress((void**)&wpack, g_wpack);
    cudaGetSymbolAddress((void**)&bpack, g_bpack);
    cudaGetSymbolAddress((void**)&qraw,  g_qraw);
    cudaGetSymbolAddress((void**)&qbuf,  g_q);
    cudaGetSymbolAddress((void**)&kmp,   g_km);
    cudaGetSymbolAddress((void**)&vmp,   g_vm);
    cudaGetSymbolAddress((void**)&attn,  g_attn);
    cudaGetSymbolAddress((void**)&hid_t, g_hid_t);
    cudaGetSymbolAddress((void**)&wo_t,  g_wo_t);

    cudaFuncSetAttribute(attn_mma, cudaFuncAttributeMaxDynamicSharedMemorySize,
                         ATTN2_BYTES);
    cudaFuncSetAttribute(tf32_gemm_bias, cudaFuncAttributeMaxDynamicSharedMemorySize,
                         GEMM_SMEM_BYTES);

    {
        long nw = (long)HD * NPACK;
        pack_w<<<(unsigned)((nw + 255) / 256), 256>>>(Wqkv, wpack);
        pack_b<<<(NPACK + 255) / 256, 256>>>(bqkv, bpack);
        int n4h = (BB * SS * HD) / 4, n4o = (HD * HD) / 4;
        cvt_tf32_vec<<<(n4h + 511) / 512, 512>>>((const float4*)hidden,
                                                 (float4*)hid_t, n4h);
        cvt_tf32_vec<<<(n4o + 511) / 512, 512>>>((const float4*)Wo,
                                                 (float4*)wo_t, n4o);
    }

    tf32_gemm_bias<<<dim3(NPACK / 128, 4096 / 128), 256, GEMM_SMEM_BYTES>>>(
        hid_t, wpack, bpack, qraw, 4096, NPACK, 2048);

    rope_split_kernel<<<BB * SS, 128>>>(qraw, qbuf, kmp, vmp);

    attn_mma<<<dim3(SS / 16, 2, BB), 256, ATTN2_BYTES>>>(
        qbuf, kmp, vmp, mask, gidx, attn);

    tf32_gemm_bias<<<dim3(2048 / 128, 4096 / 128), 256, GEMM_SMEM_BYTES>>>(
        attn, wo_t, bo, out, 4096, 2048, 2048);
}

// round 11
// speedup vs baseline: 5.5215x; 1.0249x over previous
#include <cuda_runtime.h>
#include <cuda_bf16.h>
#include <cstdint>
#include <math.h>

#define BB 2
#define SS 2048
#define HH 16
#define DD 128
#define HD 2048
#define WIN 256
#define GG 64
#define NPACK 2304   // 2048 q cols + 128 k_mean + 128 v_mean

__device__ float g_wpack[(size_t)HD * NPACK];
__device__ float g_bpack[NPACK];
__device__ float g_qraw[(size_t)BB * SS * NPACK];
__device__ float g_q[(size_t)BB * HH * SS * DD];
__device__ float g_km[(size_t)BB * SS * DD];
__device__ float g_vm[(size_t)BB * SS * DD];
__device__ float g_attn[(size_t)BB * SS * HD];
__device__ float g_hid_t[(size_t)BB * SS * HD];
__device__ float g_wo_t[(size_t)HD * HD];

__device__ __forceinline__ unsigned cvt_tf32_bits(float v) {
    unsigned t; asm("cvt.rna.tf32.f32 %0, %1;" : "=r"(t) : "f"(v)); return t;
}
__device__ __forceinline__ float cvt_tf32(float v) {
    return __uint_as_float(cvt_tf32_bits(v));
}
__device__ __forceinline__ void mma_tf32(float* acc, const unsigned* a, const unsigned* b) {
    asm volatile(
        "mma.sync.aligned.m16n8k8.row.col.f32.tf32.tf32.f32 "
        "{%0,%1,%2,%3}, {%4,%5,%6,%7}, {%8,%9}, {%0,%1,%2,%3};"
        : "+f"(acc[0]), "+f"(acc[1]), "+f"(acc[2]), "+f"(acc[3])
        : "r"(a[0]), "r"(a[1]), "r"(a[2]), "r"(a[3]), "r"(b[0]), "r"(b[1]));
}

__global__ __launch_bounds__(512)
void cvt_tf32_vec(const float4* __restrict__ in, float4* __restrict__ out, int n4)
{
    int i = blockIdx.x * blockDim.x + threadIdx.x;
    if (i < n4) {
        float4 v = in[i];
        v.x = cvt_tf32(v.x); v.y = cvt_tf32(v.y);
        v.z = cvt_tf32(v.z); v.w = cvt_tf32(v.w);
        out[i] = v;
    }
}

__global__ __launch_bounds__(256)
void pack_w(const float* __restrict__ W, float* __restrict__ Wp)
{
    long idx = (long)blockIdx.x * 256 + threadIdx.x;
    if (idx >= (long)HD * NPACK) return;
    int c = (int)(idx / NPACK), n = (int)(idx % NPACK);
    const float* row = W + (size_t)c * 6144;
    float v;
    if (n < 2048) {
        v = row[(n >> 7) * 384 + (n & 127)];
    } else {
        int off = 128 + (n - 2048);
        float s = 0.f;
#pragma unroll
        for (int h = 0; h < 16; ++h) s += row[h * 384 + off];
        v = s * 0.0625f;
    }
    Wp[idx] = cvt_tf32(v);
}

__global__ __launch_bounds__(256)
void pack_b(const float* __restrict__ bq, float* __restrict__ bp)
{
    int n = blockIdx.x * 256 + threadIdx.x;
    if (n >= NPACK) return;
    float v;
    if (n < 2048) v = bq[(n >> 7) * 384 + (n & 127)];
    else {
        int off = 128 + (n - 2048);
        float s = 0.f;
#pragma unroll
        for (int h = 0; h < 16; ++h) s += bq[h * 384 + off];
        v = s * 0.0625f;
    }
    bp[n] = v;
}

// ---------------- TF32 GEMM: BK=32, 3-stage ring (proven, round 9) ----------------
#define ASTRIDE 36
#define BSTRIDE 132
#define A_STG (128 * ASTRIDE)
#define B_STG (32 * BSTRIDE)
#define STG_FLOATS (A_STG + B_STG)
#define NSTAGE 3
#define GEMM_SMEM_BYTES (NSTAGE * STG_FLOATS * 4)

__global__ __launch_bounds__(256, 2)
void tf32_gemm_bias(const float* __restrict__ A, const float* __restrict__ B,
                    const float* __restrict__ bias, float* __restrict__ C,
                    int M, int N, int K)
{
    extern __shared__ float smem_g[];
    const int tid = threadIdx.x, lane = tid & 31, warp = tid >> 5;
    const int wm = warp >> 2, wn = warp & 3;
    const int brow = blockIdx.y, bcol = blockIdx.x;
    const float* Ab = A + (size_t)brow * 128 * K;
    const float* Bb = B + (size_t)bcol * 128;
    const int nk = K >> 5;

    float acc[4][4][4];
#pragma unroll
    for (int i = 0; i < 4; i++)
#pragma unroll
        for (int j = 0; j < 4; j++)
#pragma unroll
            for (int r = 0; r < 4; r++) acc[i][j][r] = 0.f;

    auto issue = [&](int kt) {
        int k0 = kt << 5;
        float* st = smem_g + (kt % NSTAGE) * STG_FLOATS;
#pragma unroll
        for (int l = 0; l < 4; ++l) {
            int ca = l * 256 + tid;
            int m = ca >> 3, k4 = (ca & 7) << 2;
            unsigned da = (unsigned)__cvta_generic_to_shared(st + m * ASTRIDE + k4);
            asm volatile("cp.async.cg.shared.global [%0], [%1], 16;\n"
                         :: "r"(da), "l"(Ab + (size_t)m * K + k0 + k4));
            int kk = ca >> 5, n4 = (ca & 31) << 2;
            unsigned db = (unsigned)__cvta_generic_to_shared(st + A_STG + kk * BSTRIDE + n4);
            asm volatile("cp.async.cg.shared.global [%0], [%1], 16;\n"
                         :: "r"(db), "l"(Bb + (size_t)(k0 + kk) * N + n4));
        }
    };

    const int g = lane >> 2, c = lane & 3;
    const int a_base = (wm * 64 + g) * ASTRIDE + c;
    const int b_base = c * BSTRIDE + wn * 32 + g;

    auto compute = [&](int s) {
        const float* Ast = smem_g + s * STG_FLOATS;
        const float* Bst = Ast + A_STG;
#pragma unroll
        for (int ks = 0; ks < 4; ++ks) {
            int kb = ks * 8;
            unsigned af[4][4], bf[4][2];
#pragma unroll
            for (int mil = 0; mil < 4; ++mil) {
                const float* pa = Ast + a_base + mil * (16 * ASTRIDE) + kb;
                af[mil][0] = __float_as_uint(pa[0]);
                af[mil][1] = __float_as_uint(pa[8 * ASTRIDE]);
                af[mil][2] = __float_as_uint(pa[4]);
                af[mil][3] = __float_as_uint(pa[8 * ASTRIDE + 4]);
            }
#pragma unroll
            for (int nil = 0; nil < 4; ++nil) {
                const float* pb = Bst + b_base + kb * BSTRIDE + nil * 8;
                bf[nil][0] = __float_as_uint(pb[0]);
                bf[nil][1] = __float_as_uint(pb[4 * BSTRIDE]);
            }
#pragma unroll
            for (int mil = 0; mil < 4; ++mil)
#pragma unroll
                for (int nil = 0; nil < 4; ++nil)
                    mma_tf32(acc[mil][nil], af[mil], bf[nil]);
        }
    };

    issue(0); asm volatile("cp.async.commit_group;");
    issue(1); asm volatile("cp.async.commit_group;");
    for (int kt = 0; kt < nk; ++kt) {
        asm volatile("cp.async.wait_group 1;");
        __syncthreads();
        compute(kt % NSTAGE);
        if (kt + 2 < nk) issue(kt + 2);
        asm volatile("cp.async.commit_group;");
    }

    const int tig = lane & 3;
#pragma unroll
    for (int mil = 0; mil < 4; ++mil)
#pragma unroll
        for (int nil = 0; nil < 4; ++nil) {
            int row0 = brow * 128 + wm * 64 + mil * 16 + g;
            int col  = bcol * 128 + wn * 32 + nil * 8 + tig * 2;
            float b0 = bias[col], b1 = bias[col + 1];
            *(float2*)(C + (size_t)row0 * N + col) =
                make_float2(acc[mil][nil][0] + b0, acc[mil][nil][1] + b1);
            *(float2*)(C + (size_t)(row0 + 8) * N + col) =
                make_float2(acc[mil][nil][2] + b0, acc[mil][nil][3] + b1);
        }
}

// ---------------- RoPE + split ----------------
__global__ __launch_bounds__(128)
void rope_split_kernel(const float* __restrict__ qraw, float* __restrict__ qout,
                       float* __restrict__ km, float* __restrict__ vm)
{
    int bs = blockIdx.x;
    int b = bs >> 11, s = bs & 2047;
    int d = threadIdx.x;
    const float* bp = qraw + (size_t)bs * NPACK;

    float c = 1.f, sn = 0.f;
    float sgn = (d < 16) ? -1.f : 1.f;
    if (d < 32) {
        float invf = (float)exp2(-(double)(d & 15) / 16.0 * log2(10000.0));
        float ang = (float)s * invf;
        c = (float)cos((double)ang);
        sn = (float)sin((double)ang);
    }

    float kv = bp[2048 + d];
    float vv = bp[2176 + d];
    float kp = __shfl_xor_sync(0xffffffffu, kv, 16);
    if (d < 32) kv = kv * c + sgn * kp * sn;
    km[(size_t)bs * 128 + d] = kv;
    vm[(size_t)bs * 128 + d] = vv;

#pragma unroll
    for (int h = 0; h < 16; ++h) {
        float qv = bp[h * 128 + d];
        float qp = __shfl_xor_sync(0xffffffffu, qv, 16);
        float qr = (d < 32) ? (qv * c + sgn * qp * sn) : qv;
        qout[(((size_t)(b * 16 + h)) * SS + s) * 128 + d] = qr;
    }
}

// ---------------- MMA attention: ALL 16 heads per block (512 thr, warp=head) ----------------
// K/V chunk loaded & converted ONCE per block (was twice in round 9).
#define OFF_K    0                       // K [64][132] = 8448
#define OFF_VH   8448                    // V [64][136] = 8704
#define OFF_P    17152                   // per warp 2176 floats x 16 warps
#define OFF_KPOS 51968                   // int[384]
#define OFF_KADD 52352                   // float[384]
#define ATTN2_FLOATS 52736
#define ATTN2_BYTES (ATTN2_FLOATS * 4)   // 210944 B

__global__ __launch_bounds__(512, 1)
void attn_mma(const float* __restrict__ q, const float* __restrict__ km,
              const float* __restrict__ vm, const float* __restrict__ mask,
              const int* __restrict__ gidx, float* __restrict__ out)
{
    extern __shared__ float sm[];
    int* kpos = (int*)(sm + OFF_KPOS);
    float* kadd = sm + OFF_KADD;

    const int qp0 = blockIdx.x * 16, b = blockIdx.y;
    const int tid = threadIdx.x, warp = tid >> 5, lane = tid & 31;
    const int g = lane >> 2, c2 = lane & 3, tig = c2;
    const bool caseA = (qp0 >= WIN);
    const int NCH = caseA ? 6 : ((qp0 + 79) >> 6);
    const float scale = 0.08838834764831845f;

    for (int j = tid; j < 384; j += 512) {
        int pos = 1 << 27; float ka = 0.f;
        if (caseA) {
            if (j < 64) pos = gidx[b * GG + j];
            else { int p = qp0 - 255 + (j - 64);
                   if (p < SS) { pos = p; ka = mask[b * SS + p]; } }
        } else if (j < qp0 + 16) { pos = j; ka = mask[b * SS + j]; }
        kpos[j] = pos; kadd[j] = ka;
    }

    const int h = warp;                     // warp = head
    unsigned qf[16][4];
    {
        const float* qb = q + (((size_t)(b * 16 + h)) * SS + qp0) * 128;
#pragma unroll
        for (int ks = 0; ks < 16; ++ks) {
            int d0 = ks * 8 + c2;
            qf[ks][0] = cvt_tf32_bits(qb[g * 128 + d0] * scale);
            qf[ks][1] = cvt_tf32_bits(qb[(g + 8) * 128 + d0] * scale);
            qf[ks][2] = cvt_tf32_bits(qb[g * 128 + d0 + 4] * scale);
            qf[ks][3] = cvt_tf32_bits(qb[(g + 8) * 128 + d0 + 4] * scale);
        }
    }
    __syncthreads();

    float m0 = -1e30f, m1 = -1e30f, l0 = 0.f, l1 = 0.f;
    float oacc[16][4];
#pragma unroll
    for (int dt = 0; dt < 16; ++dt)
#pragma unroll
        for (int e = 0; e < 4; ++e) oacc[dt][e] = 0.f;

    float* Pw = sm + OFF_P + warp * 2176;

    for (int ch = 0; ch < NCH; ++ch) {
        const int cb = ch << 6;
        const bool isglob = caseA && (ch == 0);

        // load K + V chunk: 512 threads, 8 threads/row, 16 floats each
        {
            int r = tid >> 3, c0 = (tid & 7) * 16;
            int pos = kpos[cb + r]; if (pos >= SS) pos = 0;
            const float* kvp = km + ((size_t)b * SS + pos) * 128 + c0;
            const float* vvp = vm + ((size_t)b * SS + pos) * 128 + c0;
            float* kd = sm + OFF_K + r * 132 + c0;
            float* vh = sm + OFF_VH + r * 136 + c0;
#pragma unroll
            for (int j = 0; j < 4; ++j) {
                float4 a = *(const float4*)(kvp + j * 4);
                a.x = cvt_tf32(a.x); a.y = cvt_tf32(a.y);
                a.z = cvt_tf32(a.z); a.w = cvt_tf32(a.w);
                *(float4*)(kd + j * 4) = a;
                float4 v = *(const float4*)(vvp + j * 4);
                v.x = cvt_tf32(v.x); v.y = cvt_tf32(v.y);
                v.z = cvt_tf32(v.z); v.w = cvt_tf32(v.w);
                *(float4*)(vh + j * 4) = v;
            }
        }
        __syncthreads();

        float S[8][4];
#pragma unroll
        for (int nt = 0; nt < 8; ++nt)
#pragma unroll
            for (int e = 0; e < 4; ++e) S[nt][e] = 0.f;
#pragma unroll
        for (int ks = 0; ks < 16; ++ks) {
#pragma unroll
            for (int nt = 0; nt < 8; ++nt) {
                const float* pk = sm + OFF_K + (nt * 8 + g) * 132 + ks * 8 + c2;
                unsigned bf[2] = {__float_as_uint(pk[0]), __float_as_uint(pk[4])};
                mma_tf32(S[nt], qf[ks], bf);
            }
        }

        float mc0 = -2e30f, mc1 = -2e30f;
#pragma unroll
        for (int nt = 0; nt < 8; ++nt) {
            int s0 = cb + nt * 8 + 2 * tig;
#pragma unroll
            for (int e = 0; e < 2; ++e) {
                int p = kpos[s0 + e]; float ka = kadd[s0 + e];
                int r0 = qp0 + g, r1 = r0 + 8;
                bool v0, v1;
                if (isglob) { v0 = p < r0 - 256; v1 = p < r1 - 256; }
                else { v0 = (p <= r0) && (p + 255 >= r0);
                       v1 = (p <= r1) && (p + 255 >= r1); }
                S[nt][e]     = v0 ? S[nt][e] + ka     : -2e30f;
                S[nt][e + 2] = v1 ? S[nt][e + 2] + ka : -2e30f;
                mc0 = fmaxf(mc0, S[nt][e]);
                mc1 = fmaxf(mc1, S[nt][e + 2]);
            }
        }
        mc0 = fmaxf(mc0, __shfl_xor_sync(~0u, mc0, 1));
        mc0 = fmaxf(mc0, __shfl_xor_sync(~0u, mc0, 2));
        mc1 = fmaxf(mc1, __shfl_xor_sync(~0u, mc1, 1));
        mc1 = fmaxf(mc1, __shfl_xor_sync(~0u, mc1, 2));
        float mn0 = fmaxf(m0, mc0), mn1 = fmaxf(m1, mc1);
        float cr0 = __expf(m0 - mn0), cr1 = __expf(m1 - mn1);
        m0 = mn0; m1 = mn1;
        float lc0 = 0.f, lc1 = 0.f;
#pragma unroll
        for (int nt = 0; nt < 8; ++nt) {
            S[nt][0] = __expf(S[nt][0] - mn0); S[nt][1] = __expf(S[nt][1] - mn0);
            S[nt][2] = __expf(S[nt][2] - mn1); S[nt][3] = __expf(S[nt][3] - mn1);
            lc0 += S[nt][0] + S[nt][1]; lc1 += S[nt][2] + S[nt][3];
        }
        lc0 += __shfl_xor_sync(~0u, lc0, 1); lc0 += __shfl_xor_sync(~0u, lc0, 2);
        lc1 += __shfl_xor_sync(~0u, lc1, 1); lc1 += __shfl_xor_sync(~0u, lc1, 2);
        l0 = l0 * cr0 + lc0; l1 = l1 * cr1 + lc1;
#pragma unroll
        for (int dt = 0; dt < 16; ++dt) {
            oacc[dt][0] *= cr0; oacc[dt][1] *= cr0;
            oacc[dt][2] *= cr1; oacc[dt][3] *= cr1;
        }
#pragma unroll
        for (int nt = 0; nt < 8; ++nt) {
            int col = nt * 8 + 2 * tig;
            float h00 = cvt_tf32(S[nt][0]), h01 = cvt_tf32(S[nt][1]);
            float h10 = cvt_tf32(S[nt][2]), h11 = cvt_tf32(S[nt][3]);
            *(float2*)(Pw + g * 68 + col)            = make_float2(h00, h01);
            *(float2*)(Pw + (g + 8) * 68 + col)      = make_float2(h10, h11);
            *(float2*)(Pw + 1088 + g * 68 + col)     =
                make_float2(cvt_tf32(S[nt][0] - h00), cvt_tf32(S[nt][1] - h01));
            *(float2*)(Pw + 1088 + (g + 8) * 68 + col) =
                make_float2(cvt_tf32(S[nt][2] - h10), cvt_tf32(S[nt][3] - h11));
        }
        __syncwarp();

#pragma unroll
        for (int pk = 0; pk < 8; ++pk) {
            const float* ph = Pw + pk * 8 + c2;
            unsigned ah[4] = {__float_as_uint(ph[g * 68]),
                              __float_as_uint(ph[(g + 8) * 68]),
                              __float_as_uint(ph[g * 68 + 4]),
                              __float_as_uint(ph[(g + 8) * 68 + 4])};
            const float* pl = ph + 1088;
            unsigned al[4] = {__float_as_uint(pl[g * 68]),
                              __float_as_uint(pl[(g + 8) * 68]),
                              __float_as_uint(pl[g * 68 + 4]),
                              __float_as_uint(pl[(g + 8) * 68 + 4])};
#pragma unroll
            for (int dt = 0; dt < 16; ++dt) {
                const float* vh = sm + OFF_VH + (pk * 8 + c2) * 136 + dt * 8 + g;
                unsigned bh[2] = {__float_as_uint(vh[0]), __float_as_uint(vh[4 * 136])};
                mma_tf32(oacc[dt], ah, bh);
                mma_tf32(oacc[dt], al, bh);
            }
        }
        __syncthreads();
    }

    float inv0 = 1.f / l0, inv1 = 1.f / l1;
    float* o0 = out + ((size_t)b * SS + qp0 + g) * HD + h * 128 + 2 * tig;
    float* o1 = out + ((size_t)b * SS + qp0 + g + 8) * HD + h * 128 + 2 * tig;
#pragma unroll
    for (int dt = 0; dt < 16; ++dt) {
        *(float2*)(o0 + dt * 8) = make_float2(cvt_tf32(oacc[dt][0] * inv0),
                                              cvt_tf32(oacc[dt][1] * inv0));
        *(float2*)(o1 + dt * 8) = make_float2(cvt_tf32(oacc[dt][2] * inv1),
                                              cvt_tf32(oacc[dt][3] * inv1));
    }
}

// ---------------------------------------------------------------------------
extern "C" void kernel_launch(void* const* d_in, const int* in_sizes, int n_in,
                              void* d_out, int out_size)
{
    const float* hidden = (const float*)d_in[0];
    const float* mask   = (const float*)d_in[1];
    const int*   gidx   = (const int*)d_in[2];
    const float* Wqkv   = (const float*)d_in[3];
    const float* bqkv   = (const float*)d_in[4];
    const float* Wo     = (const float*)d_in[5];
    const float* bo     = (const float*)d_in[6];
    float* out = (float*)d_out;

    float *wpack, *bpack, *qraw, *qbuf, *kmp, *vmp, *attn, *hid_t, *wo_t;
    cudaGetSymbolAddress((void**)&wpack, g_wpack);
    cudaGetSymbolAddress((void**)&bpack, g_bpack);
    cudaGetSymbolAddress((void**)&qraw,  g_qraw);
    cudaGetSymbolAddress((void**)&qbuf,  g_q);
    cudaGetSymbolAddress((void**)&kmp,   g_km);
    cudaGetSymbolAddress((void**)&vmp,   g_vm);
    cudaGetSymbolAddress((void**)&attn,  g_attn);
    cudaGetSymbolAddress((void**)&hid_t, g_hid_t);
    cudaGetSymbolAddress((void**)&wo_t,  g_wo_t);

    cudaFuncSetAttribute(attn_mma, cudaFuncAttributeMaxDynamicSharedMemorySize,
                         ATTN2_BYTES);
    cudaFuncSetAttribute(tf32_gemm_bias, cudaFuncAttributeMaxDynamicSharedMemorySize,
                         GEMM_SMEM_BYTES);

    {
        long nw = (long)HD * NPACK;
        pack_w<<<(unsigned)((nw + 255) / 256), 256>>>(Wqkv, wpack);
        pack_b<<<(NPACK + 255) / 256, 256>>>(bqkv, bpack);
        int n4h = (BB * SS * HD) / 4, n4o = (HD * HD) / 4;
        cvt_tf32_vec<<<(n4h + 511) / 512, 512>>>((const float4*)hidden,
                                                 (float4*)hid_t, n4h);
        cvt_tf32_vec<<<(n4o + 511) / 512, 512>>>((const float4*)Wo,
                                                 (float4*)wo_t, n4o);
    }

    tf32_gemm_bias<<<dim3(NPACK / 128, 4096 / 128), 256, GEMM_SMEM_BYTES>>>(
        hid_t, wpack, bpack, qraw, 4096, NPACK, 2048);

    rope_split_kernel<<<BB * SS, 128>>>(qraw, qbuf, kmp, vmp);

    attn_mma<<<dim3(SS / 16, BB), 512, ATTN2_BYTES>>>(
        qbuf, kmp, vmp, mask, gidx, attn);

    tf32_gemm_bias<<<dim3(2048 / 128, 4096 / 128), 256, GEMM_SMEM_BYTES>>>(
        attn, wo_t, bo, out, 4096, 2048, 2048);
}